// round 6
// baseline (speedup 1.0000x reference)
#include <cuda_runtime.h>
#include <math.h>

// ---------------------------------------------------------------------------
// VQ-VAE forward, fp32 baseline.
// Pipeline: enc1 -> enc2 -> [enc3 + VQ argmin + quantize, fused] -> dec1 ->
//           [dec2 + dec3, fused] -> finalize (vq_loss, perplexity).
// ---------------------------------------------------------------------------

#define NR   262144          // rows
#define GRID (NR / 64)       // 4096 blocks of 64 rows

// Scratch (static device memory — no allocation anywhere)
__device__ float g_h1[NR * 256];   // 256 MB : enc1 out
__device__ float g_h2[NR * 128];   // 128 MB : enc2 out, reused as dec1 out
__device__ float g_q [NR * 64];    //  64 MB : quantized latents
__device__ float g_hn[1024];       // 0.5*||codebook_j||^2
__device__ int   g_hist[1024];     // codebook usage counts
__device__ float g_msep[GRID];     // per-block sum of (q - z)^2

// ---------------------------------------------------------------------------
__global__ void k_init() { g_hist[threadIdx.x] = 0; }

__global__ void k_hn(const float* __restrict__ cb) {
    int j = blockIdx.x * 256 + threadIdx.x;   // grid 4 x 256
    float s = 0.f;
    #pragma unroll 8
    for (int d = 0; d < 64; d++) { float v = cb[j * 64 + d]; s = fmaf(v, v, s); }
    g_hn[j] = 0.5f * s;
}

// ---------------------------------------------------------------------------
// enc1: [N,9] -> relu -> [N,256].  Memory-bound; one col per thread (mod 256).
__global__ __launch_bounds__(512, 1)
void k_enc1(const float* __restrict__ X, const float* __restrict__ W,
            const float* __restrict__ B, float* __restrict__ out) {
    __shared__ float xs[64 * 12];
    int tid = threadIdx.x;
    long row0 = (long)blockIdx.x * 64;
    for (int i = tid; i < 64 * 9; i += 512) {
        int r = i / 9, k = i - r * 9;
        xs[r * 12 + k] = X[row0 * 9 + i];
    }
    int col = tid & 255;
    int rh  = tid >> 8;
    float w[9];
    float b = __ldg(&B[col]);
    #pragma unroll
    for (int k = 0; k < 9; k++) w[k] = __ldg(&W[col * 9 + k]);
    __syncthreads();
    for (int r = rh * 32; r < rh * 32 + 32; r++) {
        float acc = b;
        #pragma unroll
        for (int k = 0; k < 9; k++) acc = fmaf(xs[r * 12 + k], w[k], acc);
        out[(row0 + r) * 256 + col] = fmaxf(acc, 0.f);
    }
}

// ---------------------------------------------------------------------------
// Generic MLP layer: out[64-row tile, DOUT] = (relu)(A @ W^T + B)
// 512 threads: cg = tid&15 (16 col groups, cols strided by 16), rg = tid>>4
// (32 row groups of 2 rows). Smem stride DIN+1 => bank-conflict-free W reads.
template <int DIN, int DOUT, bool RELU>
__global__ __launch_bounds__(512, 1)
void k_mlp(const float* __restrict__ A, const float* __restrict__ W,
           const float* __restrict__ B, float* __restrict__ out) {
    constexpr int TM = 64, DP = DIN + 1, CPT = DOUT / 16;
    extern __shared__ float sm[];
    float* As = sm;                 // TM * DP
    float* Ws = sm + TM * DP;       // DOUT * DP
    int tid = threadIdx.x;
    long row0 = (long)blockIdx.x * TM;
    for (int i = tid; i < TM * DIN; i += 512) {
        int r = i / DIN, k = i - r * DIN;
        As[r * DP + k] = A[row0 * DIN + i];
    }
    for (int i = tid; i < DOUT * DIN; i += 512) {
        int c = i / DIN, k = i - c * DIN;
        Ws[c * DP + k] = W[i];
    }
    __syncthreads();
    int cg = tid & 15, rg = tid >> 4;
    float acc[2][CPT];
    #pragma unroll
    for (int j = 0; j < CPT; j++) {
        float b = __ldg(&B[cg + 16 * j]);
        acc[0][j] = b; acc[1][j] = b;
    }
    const float* ap = As + (rg * 2) * DP;
    const float* wp = Ws + cg * DP;
    #pragma unroll 4
    for (int k = 0; k < DIN; k++) {
        float a0 = ap[k], a1 = ap[DP + k];
        #pragma unroll
        for (int j = 0; j < CPT; j++) {
            float w = wp[j * 16 * DP + k];
            acc[0][j] = fmaf(a0, w, acc[0][j]);
            acc[1][j] = fmaf(a1, w, acc[1][j]);
        }
    }
    #pragma unroll
    for (int r = 0; r < 2; r++)
        #pragma unroll
        for (int j = 0; j < CPT; j++) {
            float v = acc[r][j];
            if (RELU) v = fmaxf(v, 0.f);
            out[(row0 + rg * 2 + r) * DOUT + cg + 16 * j] = v;
        }
}

// ---------------------------------------------------------------------------
// Fused enc3 + VQ: h2 tile -> z tile (smem) -> argmax(z.c - 0.5|c|^2) over
// 1024 codes in 8 tiles of 128 -> histogram, quantized gather, mse partial.
__global__ __launch_bounds__(512, 1)
void k_vq(const float* __restrict__ H, const float* __restrict__ W3,
          const float* __restrict__ B3, const float* __restrict__ CB,
          float* __restrict__ Q) {
    extern __shared__ float sm[];
    float* hs   = sm;                    // 64*129
    float* w3s  = hs  + 64 * 129;        // 64*129
    float* zs   = w3s + 64 * 129;        // 64*65
    float* cs   = zs  + 64 * 65;         // 128*65
    float* hns  = cs  + 128 * 65;        // 128
    float* red_s = hns + 128;            // 64*16
    int*   red_i = (int*)(red_s + 64 * 16);  // 64*16
    int*   idxs  = red_i + 64 * 16;          // 64
    __shared__ float warr[16];

    int tid = threadIdx.x;
    long row0 = (long)blockIdx.x * 64;
    for (int i = tid; i < 64 * 128; i += 512) {
        int r = i >> 7, k = i & 127;
        hs[r * 129 + k] = H[row0 * 128 + i];
    }
    for (int i = tid; i < 64 * 128; i += 512) {
        int c = i >> 7, k = i & 127;
        w3s[c * 129 + k] = W3[i];
    }
    __syncthreads();

    int cg = tid & 15, rg = tid >> 4;
    // --- phase A: z tile = h2 @ w3^T + b3 (no relu) ---
    {
        float acc[2][4];
        #pragma unroll
        for (int j = 0; j < 4; j++) {
            float b = __ldg(&B3[cg + 16 * j]);
            acc[0][j] = b; acc[1][j] = b;
        }
        const float* ap = hs + (rg * 2) * 129;
        const float* wp = w3s + cg * 129;
        #pragma unroll 4
        for (int k = 0; k < 128; k++) {
            float a0 = ap[k], a1 = ap[129 + k];
            #pragma unroll
            for (int j = 0; j < 4; j++) {
                float w = wp[j * 16 * 129 + k];
                acc[0][j] = fmaf(a0, w, acc[0][j]);
                acc[1][j] = fmaf(a1, w, acc[1][j]);
            }
        }
        #pragma unroll
        for (int r = 0; r < 2; r++)
            #pragma unroll
            for (int j = 0; j < 4; j++)
                zs[(rg * 2 + r) * 65 + cg + 16 * j] = acc[r][j];
    }

    // --- phase B: distance GEMM over 8 code tiles of 128 ---
    float best0 = -3.4e38f, best1 = -3.4e38f;
    int   bi0 = 0, bi1 = 0;
    for (int t = 0; t < 8; t++) {
        __syncthreads();
        for (int i = tid; i < 128 * 64; i += 512) {
            int c = i >> 6, k = i & 63;
            cs[c * 65 + k] = CB[(long)(t * 128) * 64 + i];
        }
        if (tid < 128) hns[tid] = g_hn[t * 128 + tid];
        __syncthreads();
        float acc[2][8];
        #pragma unroll
        for (int j = 0; j < 8; j++) { acc[0][j] = 0.f; acc[1][j] = 0.f; }
        const float* zp = zs + (rg * 2) * 65;
        const float* cp = cs + cg * 65;
        #pragma unroll 4
        for (int k = 0; k < 64; k++) {
            float a0 = zp[k], a1 = zp[65 + k];
            #pragma unroll
            for (int j = 0; j < 8; j++) {
                float w = cp[j * 16 * 65 + k];
                acc[0][j] = fmaf(a0, w, acc[0][j]);
                acc[1][j] = fmaf(a1, w, acc[1][j]);
            }
        }
        #pragma unroll
        for (int j = 0; j < 8; j++) {
            int gi = t * 128 + cg + 16 * j;   // ascending within thread
            float h = hns[cg + 16 * j];
            float s0 = acc[0][j] - h;
            float s1 = acc[1][j] - h;
            if (s0 > best0) { best0 = s0; bi0 = gi; }   // strict > keeps first
            if (s1 > best1) { best1 = s1; bi1 = gi; }
        }
    }

    // --- phase C: cross-colgroup reduce (tie -> smallest index) ---
    red_s[(rg * 2 + 0) * 16 + cg] = best0; red_i[(rg * 2 + 0) * 16 + cg] = bi0;
    red_s[(rg * 2 + 1) * 16 + cg] = best1; red_i[(rg * 2 + 1) * 16 + cg] = bi1;
    __syncthreads();
    if (tid < 64) {
        float bs = red_s[tid * 16];
        int   bi = red_i[tid * 16];
        #pragma unroll
        for (int c = 1; c < 16; c++) {
            float s = red_s[tid * 16 + c];
            int  ii = red_i[tid * 16 + c];
            if (s > bs || (s == bs && ii < bi)) { bs = s; bi = ii; }
        }
        idxs[tid] = bi;
        atomicAdd(&g_hist[bi], 1);
    }
    __syncthreads();

    // --- phase D: gather quantized rows, accumulate mse partial ---
    float lsum = 0.f;
    for (int i = tid; i < 64 * 64; i += 512) {
        int r = i >> 6, d = i & 63;
        int ci = idxs[r];
        float q = __ldg(&CB[(long)ci * 64 + d]);
        float z = zs[r * 65 + d];
        Q[row0 * 64 + i] = q;
        float df = q - z;
        lsum = fmaf(df, df, lsum);
    }
    #pragma unroll
    for (int o = 16; o; o >>= 1) lsum += __shfl_xor_sync(0xffffffffu, lsum, o);
    if ((tid & 31) == 0) warr[tid >> 5] = lsum;
    __syncthreads();
    if (tid == 0) {
        float s = 0.f;
        #pragma unroll
        for (int w = 0; w < 16; w++) s += warr[w];   // fixed order: deterministic
        g_msep[blockIdx.x] = s;
    }
}

// ---------------------------------------------------------------------------
// Fused dec2 (128->256, relu) + dec3 (256->9) -> x_recon straight to d_out.
__global__ __launch_bounds__(512, 1)
void k_dec23(const float* __restrict__ A, const float* __restrict__ W2,
             const float* __restrict__ B2, const float* __restrict__ W3,
             const float* __restrict__ B3, float* __restrict__ out) {
    extern __shared__ float sm[];
    float* As  = sm;            // 64*129 = 8256
    float* Ws  = sm + 8256;     // 256*129 = 33024  (ends 41280)
    float* W3s = sm + 41280;    // 9*257 = 2313
    float* d2s = sm;            // 64*260 = 16640, overlays As+Ws head after use
    int tid = threadIdx.x;
    long row0 = (long)blockIdx.x * 64;
    for (int i = tid; i < 64 * 128; i += 512) {
        int r = i >> 7, k = i & 127;
        As[r * 129 + k] = A[row0 * 128 + i];
    }
    for (int i = tid; i < 256 * 128; i += 512) {
        int c = i >> 7, k = i & 127;
        Ws[c * 129 + k] = W2[i];
    }
    for (int i = tid; i < 9 * 256; i += 512) {
        int c = i / 256, k = i - c * 256;
        W3s[c * 257 + k] = W3[i];
    }
    __syncthreads();

    int cg = tid & 15, rg = tid >> 4;
    float acc[2][16];
    #pragma unroll
    for (int j = 0; j < 16; j++) {
        float b = __ldg(&B2[cg + 16 * j]);
        acc[0][j] = b; acc[1][j] = b;
    }
    const float* ap = As + (rg * 2) * 129;
    const float* wp = Ws + cg * 129;
    #pragma unroll 4
    for (int k = 0; k < 128; k++) {
        float a0 = ap[k], a1 = ap[129 + k];
        #pragma unroll
        for (int j = 0; j < 16; j++) {
            float w = wp[j * 16 * 129 + k];
            acc[0][j] = fmaf(a0, w, acc[0][j]);
            acc[1][j] = fmaf(a1, w, acc[1][j]);
        }
    }
    __syncthreads();   // everyone done reading As/Ws before overlay
    #pragma unroll
    for (int r = 0; r < 2; r++)
        #pragma unroll
        for (int j = 0; j < 16; j++)
            d2s[(rg * 2 + r) * 260 + cg + 16 * j] = fmaxf(acc[r][j], 0.f);
    __syncthreads();

    // dec3: 64 rows x 9 cols, K = 256
    for (int e = tid; e < 64 * 9; e += 512) {
        int r = e / 9, c = e - r * 9;
        const float* dp = d2s + r * 260;
        const float* wq = W3s + c * 257;
        float s0 = __ldg(&B3[c]), s1 = 0.f;
        #pragma unroll 4
        for (int k = 0; k < 256; k += 2) {
            s0 = fmaf(dp[k],     wq[k],     s0);
            s1 = fmaf(dp[k + 1], wq[k + 1], s1);
        }
        out[row0 * 9 + e] = s0 + s1;
    }
}

// ---------------------------------------------------------------------------
__global__ void k_final(float* __restrict__ out) {
    __shared__ double sd[1024];
    __shared__ double mse_tot;
    int tid = threadIdx.x;
    double lm = 0.0;
    for (int i = tid; i < GRID; i += 1024) lm += (double)g_msep[i];
    sd[tid] = lm;
    __syncthreads();
    for (int o = 512; o; o >>= 1) {
        if (tid < o) sd[tid] += sd[tid + o];
        __syncthreads();
    }
    if (tid == 0) mse_tot = sd[0];
    __syncthreads();
    // entropy of code usage histogram (fp32 math matching reference)
    float p = (float)g_hist[tid] / 262144.0f;
    float term = p * logf(p + 1e-10f);
    sd[tid] = (double)term;
    __syncthreads();
    for (int o = 512; o; o >>= 1) {
        if (tid < o) sd[tid] += sd[tid + o];
        __syncthreads();
    }
    if (tid == 0) {
        float mse_mean = (float)(mse_tot / (262144.0 * 64.0));
        float vq_loss = 1.25f * mse_mean;   // q_latent + beta*e_latent, equal values
        float perp = expf(-(float)sd[0]);
        out[262144 * 9 + 0] = vq_loss;
        out[262144 * 9 + 1] = perp;
    }
}

// ---------------------------------------------------------------------------
extern "C" void kernel_launch(void* const* d_in, const int* in_sizes, int n_in,
                              void* d_out, int out_size) {
    const float* x   = (const float*)d_in[0];
    const float* ew1 = (const float*)d_in[1];
    const float* eb1 = (const float*)d_in[2];
    const float* ew2 = (const float*)d_in[3];
    const float* eb2 = (const float*)d_in[4];
    const float* ew3 = (const float*)d_in[5];
    const float* eb3 = (const float*)d_in[6];
    const float* dw1 = (const float*)d_in[7];
    const float* db1 = (const float*)d_in[8];
    const float* dw2 = (const float*)d_in[9];
    const float* db2 = (const float*)d_in[10];
    const float* dw3 = (const float*)d_in[11];
    const float* db3 = (const float*)d_in[12];
    const float* cb  = (const float*)d_in[13];
    float* out = (float*)d_out;

    void *p_h1, *p_h2, *p_q;
    cudaGetSymbolAddress(&p_h1, g_h1);
    cudaGetSymbolAddress(&p_h2, g_h2);
    cudaGetSymbolAddress(&p_q,  g_q);
    float* h1 = (float*)p_h1;
    float* h2 = (float*)p_h2;
    float* q  = (float*)p_q;

    const int SM_ENC2 = (64 * 257 + 128 * 257) * 4;          // 197376
    const int SM_DEC1 = (64 * 65 + 128 * 65) * 4;            // 49920
    const int SM_VQ   = (64*129 + 64*129 + 64*65 + 128*65 + 128 + 64*16*2 + 64) * 4; // 124928
    const int SM_D23  = (41280 + 9 * 257 + 16) * 4;          // 174436

    cudaFuncSetAttribute(k_mlp<256, 128, true>, cudaFuncAttributeMaxDynamicSharedMemorySize, SM_ENC2);
    cudaFuncSetAttribute(k_mlp<64, 128, true>,  cudaFuncAttributeMaxDynamicSharedMemorySize, SM_DEC1);
    cudaFuncSetAttribute(k_vq,    cudaFuncAttributeMaxDynamicSharedMemorySize, SM_VQ);
    cudaFuncSetAttribute(k_dec23, cudaFuncAttributeMaxDynamicSharedMemorySize, SM_D23);

    k_init<<<1, 1024>>>();
    k_hn<<<4, 256>>>(cb);
    k_enc1<<<GRID, 512>>>(x, ew1, eb1, h1);
    k_mlp<256, 128, true><<<GRID, 512, SM_ENC2>>>(h1, ew2, eb2, h2);
    k_vq<<<GRID, 512, SM_VQ>>>(h2, ew3, eb3, cb, q);
    k_mlp<64, 128, true><<<GRID, 512, SM_DEC1>>>(q, dw1, db1, h2);
    k_dec23<<<GRID, 512, SM_D23>>>(h2, dw2, db2, dw3, db3, out);
    k_final<<<1, 1024>>>(out);
}

// round 9
// speedup vs baseline: 2.0070x; 2.0070x over previous
#include <cuda_runtime.h>
#include <cuda_fp16.h>
#include <math.h>

#define NRR 262144
#define GRD 2048
typedef unsigned int u32;
typedef __half hf;

// ---- static scratch ----
__device__ hf g_qh [NRR*64], g_ql [NRR*64];
__device__ hf g_w2h[128*256], g_w2l[128*256];
__device__ hf g_w3h[64*128],  g_w3l[64*128];
__device__ hf g_d1h[128*64],  g_d1l[128*64];
__device__ hf g_d2h[256*128], g_d2l[256*128];
__device__ hf g_cbh[1024*64], g_cbl[1024*64];
__device__ float g_hn[1024];
__device__ int   g_hist[1024];
__device__ float g_msep[GRD];

__device__ __forceinline__ void fsp(float v, hf&h, hf&l){ h=__float2half_rn(v); l=__float2half_rn(v-__half2float(h)); }
__device__ __forceinline__ u32 hpk(hf a, hf b){ return (u32)__half_as_ushort(a) | ((u32)__half_as_ushort(b)<<16); }

#define MMA4(c,a0,a1,a2,a3,b0,b1) \
  asm volatile("mma.sync.aligned.m16n8k16.row.col.f32.f16.f16.f32 {%0,%1,%2,%3},{%4,%5,%6,%7},{%8,%9},{%0,%1,%2,%3};" \
    : "+f"((c)[0]),"+f"((c)[1]),"+f"((c)[2]),"+f"((c)[3]) \
    : "r"(a0),"r"(a1),"r"(a2),"r"(a3),"r"(b0),"r"(b1))

// K=64 chunk GEMM: A[128x64] (this warp's 16 rows at SAh/SAl, stride 72),
// B[NC*8 x 64] (stride 72). 3-product split accumulate into cc[NC*4].
template<int NC>
__device__ __forceinline__ void mma64(const hf* SAh, const hf* SAl,
                                      const hf* SBh, const hf* SBl,
                                      float* cc, int lane){
    int gi=lane>>2, ti=lane&3;
    #pragma unroll
    for(int ks=0;ks<4;ks++){
        int k0=ks*16+2*ti;
        u32 ah0=*(const u32*)(SAh+gi*72+k0),     ah1=*(const u32*)(SAh+(gi+8)*72+k0);
        u32 ah2=*(const u32*)(SAh+gi*72+k0+8),   ah3=*(const u32*)(SAh+(gi+8)*72+k0+8);
        u32 al0=*(const u32*)(SAl+gi*72+k0),     al1=*(const u32*)(SAl+(gi+8)*72+k0);
        u32 al2=*(const u32*)(SAl+gi*72+k0+8),   al3=*(const u32*)(SAl+(gi+8)*72+k0+8);
        #pragma unroll
        for(int nc=0;nc<NC;nc++){
            const hf* bh=SBh+(nc*8+gi)*72+k0;
            const hf* bl=SBl+(nc*8+gi)*72+k0;
            u32 bh0=*(const u32*)bh, bh1=*(const u32*)(bh+8);
            u32 bl0=*(const u32*)bl, bl1=*(const u32*)(bl+8);
            float* c=cc+nc*4;
            MMA4(c,ah0,ah1,ah2,ah3,bh0,bh1);
            MMA4(c,ah0,ah1,ah2,ah3,bl0,bl1);
            MMA4(c,al0,al1,al2,al3,bh0,bh1);
        }
    }
}

// stage [nrows x 64] halves global -> smem stride 72
__device__ __forceinline__ void stage64(const hf* __restrict__ g, long row0, int nrows,
                                        int gstride, int kofs, hf* dst, int tid){
    for(int i=tid;i<nrows*8;i+=256){
        int r=i>>3, s=i&7;
        *(uint4*)(dst+r*72+s*8) = *(const uint4*)(g+(row0+r)*(long)gstride+kofs+s*8);
    }
}

__device__ __forceinline__ void top2ins(float s,int i,float&s1,int&i1,float&s2,int&i2){
    if(s>s1||(s==s1&&i<i1)){ s2=s1;i2=i1;s1=s;i1=i; }
    else if(s>s2||(s==s2&&i<i2)){ s2=s;i2=i; }
}

// smem byte offsets
#define SA0H 0
#define SA0L 18432
#define SA1H 36864
#define SA1L 55296
#define SBH  73728
#define SBL  110592
#define AUX  147456

// ---------------- prep ----------------
__global__ void k_prep(const float* __restrict__ w2, const float* __restrict__ w3,
                       const float* __restrict__ d1, const float* __restrict__ d2,
                       const float* __restrict__ cb){
    int i=blockIdx.x*256+threadIdx.x;
    if(i<128*256) fsp(w2[i],g_w2h[i],g_w2l[i]);
    if(i<64*128)  fsp(w3[i],g_w3h[i],g_w3l[i]);
    if(i<128*64)  fsp(d1[i],g_d1h[i],g_d1l[i]);
    if(i<256*128) fsp(d2[i],g_d2h[i],g_d2l[i]);
    if(i<1024*64) fsp(cb[i],g_cbh[i],g_cbl[i]);
    if(i<1024){
        float s=0.f;
        #pragma unroll 8
        for(int d=0;d<64;d++){ float v=cb[i*64+d]; s=fmaf(v,v,s); }
        g_hn[i]=0.5f*s; g_hist[i]=0;
    }
}

// ---------------- fused encoder + VQ ----------------
__global__ __launch_bounds__(256,1)
void k_enc(const float* __restrict__ X, const float* __restrict__ W1,
           const float* __restrict__ B1, const float* __restrict__ B2,
           const float* __restrict__ B3, const float* __restrict__ CB){
    extern __shared__ char sm[];
    hf* sa0h=(hf*)(sm+SA0H); hf* sa0l=(hf*)(sm+SA0L);
    hf* sa1h=(hf*)(sm+SA1H); hf* sa1l=(hf*)(sm+SA1L);
    hf* sbh =(hf*)(sm+SBH);  hf* sbl =(hf*)(sm+SBL);
    float* zbuf=(float*)(sm+AUX);          // 128*68
    float* xs  =(float*)(sm+AUX+34816);    // 128*12
    float* w1s =(float*)(sm+AUX+40960);    // 256*9
    __shared__ float warr[8];
    int tid=threadIdx.x, warp=tid>>5, lane=tid&31;
    int gi=lane>>2, ti=lane&3, r0=warp*16+gi;
    long row0=(long)blockIdx.x*128;

    for(int i=tid;i<128*9;i+=256){ int r=i/9,k=i-r*9; xs[r*12+k]=X[row0*9+i]; }
    for(int i=tid;i<256*9;i+=256) w1s[i]=W1[i];
    __syncthreads();

    // ---- enc2 (K=256, 4 chunks; A=enc1 computed on the fly) ----
    float c2[64];
    #pragma unroll
    for(int j=0;j<64;j++) c2[j]=0.f;
    for(int ch=0;ch<4;ch++){
        __syncthreads();
        for(int p=tid;p<128*32;p+=256){
            int r=p>>5, cp=p&31, c0=ch*64+2*cp;
            float a0=__ldg(&B1[c0]), a1=__ldg(&B1[c0+1]);
            #pragma unroll
            for(int k=0;k<9;k++){ float x=xs[r*12+k]; a0=fmaf(x,w1s[c0*9+k],a0); a1=fmaf(x,w1s[(c0+1)*9+k],a1); }
            a0=fmaxf(a0,0.f); a1=fmaxf(a1,0.f);
            hf h0,l0,h1,l1; fsp(a0,h0,l0); fsp(a1,h1,l1);
            *(u32*)(sa0h+r*72+2*cp)=hpk(h0,h1);
            *(u32*)(sa0l+r*72+2*cp)=hpk(l0,l1);
        }
        stage64(g_w2h,0,128,256,ch*64,sbh,tid);
        stage64(g_w2l,0,128,256,ch*64,sbl,tid);
        __syncthreads();
        mma64<16>(sa0h+warp*16*72, sa0l+warp*16*72, sbh, sbl, c2, lane);
    }
    __syncthreads();
    // h2 = relu(c2+b2) -> split planes (cols 0-63 -> SA0, 64-127 -> SA1)
    #pragma unroll
    for(int nc=0;nc<16;nc++){
        int c=nc*8+2*ti;
        float v0=fmaxf(c2[nc*4+0]+__ldg(&B2[c]),0.f),   v1=fmaxf(c2[nc*4+1]+__ldg(&B2[c+1]),0.f);
        float v2=fmaxf(c2[nc*4+2]+__ldg(&B2[c]),0.f),   v3=fmaxf(c2[nc*4+3]+__ldg(&B2[c+1]),0.f);
        hf h0,l0,h1,l1; int off=c&63;
        hf* dh=(c<64)?sa0h:sa1h; hf* dl=(c<64)?sa0l:sa1l;
        fsp(v0,h0,l0); fsp(v1,h1,l1);
        *(u32*)(dh+r0*72+off)=hpk(h0,h1); *(u32*)(dl+r0*72+off)=hpk(l0,l1);
        fsp(v2,h0,l0); fsp(v3,h1,l1);
        *(u32*)(dh+(r0+8)*72+off)=hpk(h0,h1); *(u32*)(dl+(r0+8)*72+off)=hpk(l0,l1);
    }
    __syncthreads();
    // ---- enc3 (K=128, 2 chunks) ----
    float c3[32];
    #pragma unroll
    for(int j=0;j<32;j++) c3[j]=0.f;
    for(int ch=0;ch<2;ch++){
        __syncthreads();
        stage64(g_w3h,0,64,128,ch*64,sbh,tid);
        stage64(g_w3l,0,64,128,ch*64,sbl,tid);
        __syncthreads();
        const hf* ah=(ch?sa1h:sa0h)+warp*16*72; const hf* al=(ch?sa1l:sa0l)+warp*16*72;
        mma64<8>(ah,al,sbh,sbl,c3,lane);
    }
    __syncthreads();
    // z -> zbuf fp32
    #pragma unroll
    for(int nc=0;nc<8;nc++){
        int c=nc*8+2*ti;
        zbuf[r0*68+c]    =c3[nc*4+0]+__ldg(&B3[c]);
        zbuf[r0*68+c+1]  =c3[nc*4+1]+__ldg(&B3[c+1]);
        zbuf[(r0+8)*68+c]  =c3[nc*4+2]+__ldg(&B3[c]);
        zbuf[(r0+8)*68+c+1]=c3[nc*4+3]+__ldg(&B3[c+1]);
    }
    __syncthreads();
    // restage z splits -> SA0
    for(int p=tid;p<128*32;p+=256){
        int r=p>>5, cp=p&31;
        float z0=zbuf[r*68+2*cp], z1=zbuf[r*68+2*cp+1];
        hf h0,l0,h1,l1; fsp(z0,h0,l0); fsp(z1,h1,l1);
        *(u32*)(sa0h+r*72+2*cp)=hpk(h0,h1);
        *(u32*)(sa0l+r*72+2*cp)=hpk(l0,l1);
    }
    // ---- VQ scan: 8 chunks of 128 codes ----
    float s1[2]={-3.4e38f,-3.4e38f}, s2[2]={-3.4e38f,-3.4e38f};
    int   i1[2]={0,0}, i2[2]={0,0};
    for(int t=0;t<8;t++){
        __syncthreads();
        stage64(g_cbh,(long)t*128,128,64,0,sbh,tid);
        stage64(g_cbl,(long)t*128,128,64,0,sbl,tid);
        __syncthreads();
        float cv[64];
        #pragma unroll
        for(int j=0;j<64;j++) cv[j]=0.f;
        mma64<16>(sa0h+warp*16*72, sa0l+warp*16*72, sbh, sbl, cv, lane);
        #pragma unroll
        for(int nc=0;nc<16;nc++){
            #pragma unroll
            for(int cc=0;cc<2;cc++){
                int col=t*128+nc*8+2*ti+cc;
                float hn=__ldg(&g_hn[col]);
                top2ins(cv[nc*4+cc]-hn,  col, s1[0],i1[0],s2[0],i2[0]);
                top2ins(cv[nc*4+2+cc]-hn,col, s1[1],i1[1],s2[1],i2[1]);
            }
        }
    }
    // merge top2 across ti lanes (xor 1, 2)
    #pragma unroll
    for(int off=1;off<=2;off<<=1){
        #pragma unroll
        for(int s=0;s<2;s++){
            float os1=__shfl_xor_sync(0xffffffffu,s1[s],off);
            int   oi1=__shfl_xor_sync(0xffffffffu,i1[s],off);
            float os2=__shfl_xor_sync(0xffffffffu,s2[s],off);
            int   oi2=__shfl_xor_sync(0xffffffffu,i2[s],off);
            top2ins(os1,oi1,s1[s],i1[s],s2[s],i2[s]);
            top2ins(os2,oi2,s1[s],i1[s],s2[s],i2[s]);
        }
    }
    float lsum=0.f;
    if(ti==0){
        u32* qh=(u32*)g_qh; u32* ql=(u32*)g_ql;
        #pragma unroll
        for(int s=0;s<2;s++){
            int row=r0+s*8;
            const float* z=&zbuf[row*68];
            float da=0.f,db=0.f;
            int ca=i1[s], cb=i2[s];
            for(int q=0;q<16;q++){
                float4 v1=__ldg((const float4*)&CB[(long)ca*64+q*4]);
                float4 v2=__ldg((const float4*)&CB[(long)cb*64+q*4]);
                float z0=z[q*4],z1=z[q*4+1],z2=z[q*4+2],z3=z[q*4+3];
                da=fmaf(v1.x-z0,v1.x-z0,da); da=fmaf(v1.y-z1,v1.y-z1,da);
                da=fmaf(v1.z-z2,v1.z-z2,da); da=fmaf(v1.w-z3,v1.w-z3,da);
                db=fmaf(v2.x-z0,v2.x-z0,db); db=fmaf(v2.y-z1,v2.y-z1,db);
                db=fmaf(v2.z-z2,v2.z-z2,db); db=fmaf(v2.w-z3,v2.w-z3,db);
            }
            int cw; float dw;
            if(da<db||(da==db&&ca<cb)){ cw=ca; dw=da; } else { cw=cb; dw=db; }
            atomicAdd(&g_hist[cw],1);
            lsum+=dw;
            long gr=row0+row;
            for(int q=0;q<16;q++){
                float4 v=__ldg((const float4*)&CB[(long)cw*64+q*4]);
                hf h0,l0,h1,l1,h2,l2,h3,l3;
                fsp(v.x,h0,l0); fsp(v.y,h1,l1); fsp(v.z,h2,l2); fsp(v.w,h3,l3);
                qh[gr*32+q*2]  =hpk(h0,h1); qh[gr*32+q*2+1]=hpk(h2,h3);
                ql[gr*32+q*2]  =hpk(l0,l1); ql[gr*32+q*2+1]=hpk(l2,l3);
            }
        }
    }
    #pragma unroll
    for(int o=16;o;o>>=1) lsum+=__shfl_xor_sync(0xffffffffu,lsum,o);
    if(lane==0) warr[warp]=lsum;
    __syncthreads();
    if(tid==0){
        float s=0.f;
        #pragma unroll
        for(int w=0;w<8;w++) s+=warr[w];
        g_msep[blockIdx.x]=s;
    }
}

// ---------------- fused decoder ----------------
__global__ __launch_bounds__(256,1)
void k_dec(const float* __restrict__ B1, const float* __restrict__ B2,
           const float* __restrict__ W3, const float* __restrict__ B3,
           float* __restrict__ out){
    extern __shared__ char sm[];
    hf* sa0h=(hf*)(sm+SA0H); hf* sa0l=(hf*)(sm+SA0L);
    hf* sa1h=(hf*)(sm+SA1H); hf* sa1l=(hf*)(sm+SA1L);
    hf* sbh =(hf*)(sm+SBH);  hf* sbl =(hf*)(sm+SBL);
    float* w3s=(float*)(sm+AUX);   // 9*256
    int tid=threadIdx.x, warp=tid>>5, lane=tid&31;
    int gi=lane>>2, ti=lane&3, r0=warp*16+gi;
    long row0=(long)blockIdx.x*128;

    for(int i=tid;i<9*256;i+=256) w3s[i]=W3[i];
    stage64(g_qh,row0,128,64,0,sa0h,tid);
    stage64(g_ql,row0,128,64,0,sa0l,tid);
    stage64(g_d1h,0,128,64,0,sbh,tid);
    stage64(g_d1l,0,128,64,0,sbl,tid);
    __syncthreads();
    // dec1 (K=64)
    float c1[64];
    #pragma unroll
    for(int j=0;j<64;j++) c1[j]=0.f;
    mma64<16>(sa0h+warp*16*72, sa0l+warp*16*72, sbh, sbl, c1, lane);
    __syncthreads();
    // d1 = relu(+b1) -> split planes SA0/SA1
    #pragma unroll
    for(int nc=0;nc<16;nc++){
        int c=nc*8+2*ti;
        float v0=fmaxf(c1[nc*4+0]+__ldg(&B1[c]),0.f),   v1=fmaxf(c1[nc*4+1]+__ldg(&B1[c+1]),0.f);
        float v2=fmaxf(c1[nc*4+2]+__ldg(&B1[c]),0.f),   v3=fmaxf(c1[nc*4+3]+__ldg(&B1[c+1]),0.f);
        hf h0,l0,h1,l1; int off=c&63;
        hf* dh=(c<64)?sa0h:sa1h; hf* dl=(c<64)?sa0l:sa1l;
        fsp(v0,h0,l0); fsp(v1,h1,l1);
        *(u32*)(dh+r0*72+off)=hpk(h0,h1); *(u32*)(dl+r0*72+off)=hpk(l0,l1);
        fsp(v2,h0,l0); fsp(v3,h1,l1);
        *(u32*)(dh+(r0+8)*72+off)=hpk(h0,h1); *(u32*)(dl+(r0+8)*72+off)=hpk(l0,l1);
    }
    // dec2 (K=128, 2 chunks, N=256)
    float c2[128];
    #pragma unroll
    for(int j=0;j<128;j++) c2[j]=0.f;
    for(int ch=0;ch<2;ch++){
        __syncthreads();
        stage64(g_d2h,0,256,128,ch*64,sbh,tid);
        stage64(g_d2l,0,256,128,ch*64,sbl,tid);
        __syncthreads();
        const hf* ah=(ch?sa1h:sa0h)+warp*16*72; const hf* al=(ch?sa1l:sa0l)+warp*16*72;
        mma64<32>(ah,al,sbh,sbl,c2,lane);
    }
    // dec3: per-thread partials over its 64 cols (x2 rows), reduce across ti
    float part[2][9];
    #pragma unroll
    for(int s=0;s<2;s++)
        #pragma unroll
        for(int j=0;j<9;j++) part[s][j]=0.f;
    #pragma unroll
    for(int nc=0;nc<32;nc++){
        #pragma unroll
        for(int cc=0;cc<2;cc++){
            int c=nc*8+2*ti+cc;
            float b=__ldg(&B2[c]);
            float v0=fmaxf(c2[nc*4+cc]+b,0.f);
            float v1=fmaxf(c2[nc*4+2+cc]+b,0.f);
            #pragma unroll
            for(int j=0;j<9;j++){
                float w=w3s[j*256+c];
                part[0][j]=fmaf(v0,w,part[0][j]);
                part[1][j]=fmaf(v1,w,part[1][j]);
            }
        }
    }
    #pragma unroll
    for(int off=1;off<=2;off<<=1)
        #pragma unroll
        for(int s=0;s<2;s++)
            #pragma unroll
            for(int j=0;j<9;j++) part[s][j]+=__shfl_xor_sync(0xffffffffu,part[s][j],off);
    if(ti==0){
        #pragma unroll
        for(int s=0;s<2;s++){
            long row=row0+r0+s*8;
            #pragma unroll
            for(int j=0;j<9;j++) out[row*9+j]=part[s][j]+__ldg(&B3[j]);
        }
    }
}

// ---------------- finalize ----------------
__global__ void k_final(float* __restrict__ out){
    __shared__ double sd[1024];
    __shared__ double mt;
    int tid=threadIdx.x;
    sd[tid]=(double)g_msep[tid]+(double)g_msep[tid+1024];
    __syncthreads();
    for(int o=512;o;o>>=1){ if(tid<o) sd[tid]+=sd[tid+o]; __syncthreads(); }
    if(tid==0) mt=sd[0];
    __syncthreads();
    float p=(float)g_hist[tid]/262144.0f;
    sd[tid]=(double)(p*logf(p+1e-10f));
    __syncthreads();
    for(int o=512;o;o>>=1){ if(tid<o) sd[tid]+=sd[tid+o]; __syncthreads(); }
    if(tid==0){
        float mse=(float)(mt/(262144.0*64.0));
        out[262144*9+0]=1.25f*mse;
        out[262144*9+1]=expf(-(float)sd[0]);
    }
}

// ---------------------------------------------------------------------------
extern "C" void kernel_launch(void* const* d_in, const int* in_sizes, int n_in,
                              void* d_out, int out_size){
    const float* x  =(const float*)d_in[0];
    const float* ew1=(const float*)d_in[1];  const float* eb1=(const float*)d_in[2];
    const float* ew2=(const float*)d_in[3];  const float* eb2=(const float*)d_in[4];
    const float* ew3=(const float*)d_in[5];  const float* eb3=(const float*)d_in[6];
    const float* dw1=(const float*)d_in[7];  const float* db1=(const float*)d_in[8];
    const float* dw2=(const float*)d_in[9];  const float* db2=(const float*)d_in[10];
    const float* dw3=(const float*)d_in[11]; const float* db3=(const float*)d_in[12];
    const float* cb =(const float*)d_in[13];
    float* out=(float*)d_out;

    const int SM_ENC = AUX + 34816 + 6144 + 9216;   // 197632
    const int SM_DEC = AUX + 9216;                  // 156672
    cudaFuncSetAttribute(k_enc, cudaFuncAttributeMaxDynamicSharedMemorySize, SM_ENC);
    cudaFuncSetAttribute(k_dec, cudaFuncAttributeMaxDynamicSharedMemorySize, SM_DEC);

    k_prep<<<256,256>>>(ew2, ew3, dw1, dw2, cb);
    k_enc<<<GRD,256,SM_ENC>>>(x, ew1, eb1, eb2, eb3, cb);
    k_dec<<<GRD,256,SM_DEC>>>(db1, db2, dw3, db3, out);
    k_final<<<1,1024>>>(out);
}

// round 10
// speedup vs baseline: 2.5462x; 1.2687x over previous
#include <cuda_runtime.h>
#include <cuda_fp16.h>
#include <math.h>

#define NRR 262144
#define GRD 2048
typedef unsigned int u32;
typedef __half hf;

// ---- static scratch (weights/codebook split planes only) ----
__device__ hf g_w2h[128*256], g_w2l[128*256];
__device__ hf g_w3h[64*128],  g_w3l[64*128];
__device__ hf g_d1h[128*64],  g_d1l[128*64];
__device__ hf g_d2h[256*128], g_d2l[256*128];
__device__ hf g_cbh[1024*64], g_cbl[1024*64];
__device__ float g_hn[1024];
__device__ int   g_hist[1024];
__device__ float g_msep[GRD];

__device__ __forceinline__ void fsp(float v, hf&h, hf&l){ h=__float2half_rn(v); l=__float2half_rn(v-__half2float(h)); }
__device__ __forceinline__ u32 hpk(hf a, hf b){ return (u32)__half_as_ushort(a) | ((u32)__half_as_ushort(b)<<16); }
__device__ __forceinline__ u32 smem_u32(const void* p){
    u32 a; asm("{ .reg .u64 t; cvta.to.shared.u64 t, %1; cvt.u32.u64 %0, t; }":"=r"(a):"l"(p)); return a;
}

#define MMA4(c,a0,a1,a2,a3,b0,b1) \
  asm volatile("mma.sync.aligned.m16n8k16.row.col.f32.f16.f16.f32 {%0,%1,%2,%3},{%4,%5,%6,%7},{%8,%9},{%0,%1,%2,%3};" \
    : "+f"((c)[0]),"+f"((c)[1]),"+f"((c)[2]),"+f"((c)[3]) \
    : "r"(a0),"r"(a1),"r"(a2),"r"(a3),"r"(b0),"r"(b1))

// 3-product split GEMM over K=64 chunk (A hi+lo, B hi+lo), smem stride 72 halves
template<int NC>
__device__ __forceinline__ void mma3(const hf* SAh, const hf* SAl,
                                     const hf* SBh, const hf* SBl, float* cc, int lane){
    int gi=lane>>2, ti=lane&3;
    #pragma unroll
    for(int ks=0;ks<4;ks++){
        int k0=ks*16+2*ti;
        u32 ah0=*(const u32*)(SAh+gi*72+k0),   ah1=*(const u32*)(SAh+(gi+8)*72+k0);
        u32 ah2=*(const u32*)(SAh+gi*72+k0+8), ah3=*(const u32*)(SAh+(gi+8)*72+k0+8);
        u32 al0=*(const u32*)(SAl+gi*72+k0),   al1=*(const u32*)(SAl+(gi+8)*72+k0);
        u32 al2=*(const u32*)(SAl+gi*72+k0+8), al3=*(const u32*)(SAl+(gi+8)*72+k0+8);
        #pragma unroll
        for(int nc=0;nc<NC;nc++){
            const hf* bh=SBh+(nc*8+gi)*72+k0;
            const hf* bl=SBl+(nc*8+gi)*72+k0;
            u32 bh0=*(const u32*)bh, bh1=*(const u32*)(bh+8);
            u32 bl0=*(const u32*)bl, bl1=*(const u32*)(bl+8);
            float* c=cc+nc*4;
            MMA4(c,ah0,ah1,ah2,ah3,bh0,bh1);
            MMA4(c,ah0,ah1,ah2,ah3,bl0,bl1);
            MMA4(c,al0,al1,al2,al3,bh0,bh1);
        }
    }
}
// 2-product: A single fp16 plane, B hi+lo
template<int NC>
__device__ __forceinline__ void mma2(const hf* SAh,
                                     const hf* SBh, const hf* SBl, float* cc, int lane){
    int gi=lane>>2, ti=lane&3;
    #pragma unroll
    for(int ks=0;ks<4;ks++){
        int k0=ks*16+2*ti;
        u32 a0=*(const u32*)(SAh+gi*72+k0),   a1=*(const u32*)(SAh+(gi+8)*72+k0);
        u32 a2=*(const u32*)(SAh+gi*72+k0+8), a3=*(const u32*)(SAh+(gi+8)*72+k0+8);
        #pragma unroll
        for(int nc=0;nc<NC;nc++){
            const hf* bh=SBh+(nc*8+gi)*72+k0;
            const hf* bl=SBl+(nc*8+gi)*72+k0;
            u32 bh0=*(const u32*)bh, bh1=*(const u32*)(bh+8);
            u32 bl0=*(const u32*)bl, bl1=*(const u32*)(bl+8);
            float* c=cc+nc*4;
            MMA4(c,a0,a1,a2,a3,bh0,bh1);
            MMA4(c,a0,a1,a2,a3,bl0,bl1);
        }
    }
}

__device__ __forceinline__ void top2ins(float s,int i,float&s1,int&i1,float&s2,int&i2){
    if(s>s1||(s==s1&&i<i1)){ s2=s1;i2=i1;s1=s;i1=i; }
    else if(s>s2||(s==s2&&i<i2)){ s2=s;i2=i; }
}

// smem byte offsets
#define SA0H 0
#define SA0L 18432
#define SA1H 36864
#define SA1L 55296
#define SBH0 73728
#define SBL0 92160
#define SBH1 110592
#define SBL1 129024
#define ZB   147456
#define W3S  182272
#define SMTOT 191488

// B-chunk schedule: 0-3 w2 | 4-5 w3 | 6-13 cb | 14 d1 | 15-18 d2
__device__ __forceinline__ void issue_chunk(int ci, u32 smb, int tid){
    if(ci>18) return;
    u32 dh = smb + ((ci&1)?SBH1:SBH0);
    u32 dl = smb + ((ci&1)?SBL1:SBL0);
    const hf *gh,*gl; long r0=0; int gs,ko,nr=128;
    if(ci<4){ gh=g_w2h; gl=g_w2l; gs=256; ko=ci*64; }
    else if(ci<6){ gh=g_w3h; gl=g_w3l; gs=128; ko=(ci-4)*64; nr=64; }
    else if(ci<14){ gh=g_cbh; gl=g_cbl; gs=64; ko=0; r0=(long)(ci-6)*128; }
    else if(ci==14){ gh=g_d1h; gl=g_d1l; gs=64; ko=0; }
    else { int t=ci-15; gh=g_d2h; gl=g_d2l; gs=128; r0=(long)(t>>1)*128; ko=(t&1)*64; }
    for(int i=tid;i<nr*8;i+=256){
        int r=i>>3, s=i&7;
        const hf* src=gh+(r0+r)*(long)gs+ko+s*8;
        asm volatile("cp.async.ca.shared.global [%0], [%1], 16;"::"r"(dh+(u32)(r*144+s*16)),"l"(src):"memory");
    }
    for(int i=tid;i<nr*8;i+=256){
        int r=i>>3, s=i&7;
        const hf* src=gl+(r0+r)*(long)gs+ko+s*8;
        asm volatile("cp.async.ca.shared.global [%0], [%1], 16;"::"r"(dl+(u32)(r*144+s*16)),"l"(src):"memory");
    }
    asm volatile("cp.async.commit_group;":::"memory");
}
__device__ __forceinline__ void pipe_wait(int ci){
    if(ci<18) asm volatile("cp.async.wait_group 1;":::"memory");
    else      asm volatile("cp.async.wait_group 0;":::"memory");
    __syncthreads();
}

// ---------------- prep ----------------
__global__ void k_prep(const float* __restrict__ w2, const float* __restrict__ w3,
                       const float* __restrict__ d1, const float* __restrict__ d2,
                       const float* __restrict__ cb){
    int i=blockIdx.x*256+threadIdx.x;
    if(i<128*256) fsp(w2[i],g_w2h[i],g_w2l[i]);
    if(i<64*128)  fsp(w3[i],g_w3h[i],g_w3l[i]);
    if(i<128*64)  fsp(d1[i],g_d1h[i],g_d1l[i]);
    if(i<256*128) fsp(d2[i],g_d2h[i],g_d2l[i]);
    if(i<1024*64) fsp(cb[i],g_cbh[i],g_cbl[i]);
    if(i<1024){
        float s=0.f;
        #pragma unroll 8
        for(int d=0;d<64;d++){ float v=cb[i*64+d]; s=fmaf(v,v,s); }
        g_hn[i]=0.5f*s; g_hist[i]=0;
    }
}

// ---------------- fused everything ----------------
__global__ __launch_bounds__(256,1)
void k_main(const float* __restrict__ X,  const float* __restrict__ W1,
            const float* __restrict__ B1, const float* __restrict__ B2,
            const float* __restrict__ B3e,const float* __restrict__ CB,
            const float* __restrict__ DB1,const float* __restrict__ DB2,
            const float* __restrict__ W3d,const float* __restrict__ DB3,
            float* __restrict__ out){
    extern __shared__ char sm[];
    hf* sa0h=(hf*)(sm+SA0H); hf* sa0l=(hf*)(sm+SA0L);
    hf* sa1h=(hf*)(sm+SA1H); hf* sa1l=(hf*)(sm+SA1L);
    float* zbuf=(float*)(sm+ZB);       // 128*68 fp32, overlays xs/w1s after enc2
    float* xs  =(float*)(sm+ZB);       // 128*12
    float* w1s =(float*)(sm+ZB+6144);  // 256*9
    float* w3s =(float*)(sm+W3S);      // 9*256
    __shared__ float warr[8];
    u32 smb=smem_u32(sm);
    int tid=threadIdx.x, warp=tid>>5, lane=tid&31;
    int gi=lane>>2, ti=lane&3, r0w=warp*16, r0=r0w+gi;
    long row0=(long)blockIdx.x*128;

    issue_chunk(0,smb,tid);
    issue_chunk(1,smb,tid);
    for(int i=tid;i<128*9;i+=256){ int r=i/9,k=i-r*9; xs[r*12+k]=X[row0*9+i]; }
    for(int i=tid;i<256*9;i+=256) w1s[i]=W1[i];
    for(int i=tid;i<9*256;i+=256) w3s[i]=W3d[i];
    __syncthreads();

    // ===== enc2 (K=256, 4 chunks; enc1 computed on the fly, 3-product) =====
    float acc[64];
    #pragma unroll
    for(int j=0;j<64;j++) acc[j]=0.f;
    for(int ch=0;ch<4;ch++){
        for(int p=tid;p<128*32;p+=256){
            int r=p>>5, cp=p&31, c0=ch*64+2*cp;
            float a0=__ldg(&B1[c0]), a1=__ldg(&B1[c0+1]);
            #pragma unroll
            for(int k=0;k<9;k++){ float xv=xs[r*12+k]; a0=fmaf(xv,w1s[c0*9+k],a0); a1=fmaf(xv,w1s[(c0+1)*9+k],a1); }
            a0=fmaxf(a0,0.f); a1=fmaxf(a1,0.f);
            hf h0,l0,h1,l1; fsp(a0,h0,l0); fsp(a1,h1,l1);
            *(u32*)(sa0h+r*72+2*cp)=hpk(h0,h1);
            *(u32*)(sa0l+r*72+2*cp)=hpk(l0,l1);
        }
        pipe_wait(ch);
        mma3<16>(sa0h+r0w*72, sa0l+r0w*72,
                 (const hf*)(sm+((ch&1)?SBH1:SBH0)), (const hf*)(sm+((ch&1)?SBL1:SBL0)), acc, lane);
        __syncthreads();
        issue_chunk(ch+2,smb,tid);
    }
    // h2 = relu(acc+b2) -> split planes SA0(0-63)/SA1(64-127)
    #pragma unroll
    for(int nc=0;nc<16;nc++){
        int c=nc*8+2*ti;
        float b0=__ldg(&B2[c]), b1=__ldg(&B2[c+1]);
        float v0=fmaxf(acc[nc*4+0]+b0,0.f), v1=fmaxf(acc[nc*4+1]+b1,0.f);
        float v2=fmaxf(acc[nc*4+2]+b0,0.f), v3=fmaxf(acc[nc*4+3]+b1,0.f);
        int off=c&63; hf* dh=(c<64)?sa0h:sa1h; hf* dl=(c<64)?sa0l:sa1l;
        hf h0,l0,h1,l1;
        fsp(v0,h0,l0); fsp(v1,h1,l1);
        *(u32*)(dh+r0*72+off)=hpk(h0,h1); *(u32*)(dl+r0*72+off)=hpk(l0,l1);
        fsp(v2,h0,l0); fsp(v3,h1,l1);
        *(u32*)(dh+(r0+8)*72+off)=hpk(h0,h1); *(u32*)(dl+(r0+8)*72+off)=hpk(l0,l1);
    }
    // ===== enc3 (K=128, 2 chunks, 3-product, N=64) =====
    float c3[32];
    #pragma unroll
    for(int j=0;j<32;j++) c3[j]=0.f;
    for(int ch=0;ch<2;ch++){
        pipe_wait(4+ch);
        const hf* ah=(ch?sa1h:sa0h)+r0w*72; const hf* al=(ch?sa1l:sa0l)+r0w*72;
        mma3<8>(ah,al,(const hf*)(sm+(((4+ch)&1)?SBH1:SBH0)),(const hf*)(sm+(((4+ch)&1)?SBL1:SBL0)),c3,lane);
        __syncthreads();
        issue_chunk(6+ch,smb,tid);
    }
    // z -> zbuf fp32 + fp16 plane in SA0H
    #pragma unroll
    for(int nc=0;nc<8;nc++){
        int c=nc*8+2*ti;
        float b0=__ldg(&B3e[c]), b1=__ldg(&B3e[c+1]);
        float z00=c3[nc*4+0]+b0, z01=c3[nc*4+1]+b1;
        float z10=c3[nc*4+2]+b0, z11=c3[nc*4+3]+b1;
        zbuf[r0*68+c]=z00; zbuf[r0*68+c+1]=z01;
        zbuf[(r0+8)*68+c]=z10; zbuf[(r0+8)*68+c+1]=z11;
        *(u32*)(sa0h+r0*72+c)=hpk(__float2half_rn(z00),__float2half_rn(z01));
        *(u32*)(sa0h+(r0+8)*72+c)=hpk(__float2half_rn(z10),__float2half_rn(z11));
    }
    // ===== VQ scan (2-product, 8 code tiles of 128) =====
    float s1[2]={-3.4e38f,-3.4e38f}, s2v[2]={-3.4e38f,-3.4e38f};
    int   i1[2]={0,0}, i2[2]={0,0};
    for(int t=0;t<8;t++){
        pipe_wait(6+t);
        float cv[64];
        #pragma unroll
        for(int j=0;j<64;j++) cv[j]=0.f;
        mma2<16>(sa0h+r0w*72,(const hf*)(sm+(((6+t)&1)?SBH1:SBH0)),(const hf*)(sm+(((6+t)&1)?SBL1:SBL0)),cv,lane);
        #pragma unroll
        for(int nc=0;nc<16;nc++){
            #pragma unroll
            for(int cc=0;cc<2;cc++){
                int col=t*128+nc*8+2*ti+cc;
                float hn=__ldg(&g_hn[col]);
                top2ins(cv[nc*4+cc]-hn,  col, s1[0],i1[0],s2v[0],i2[0]);
                top2ins(cv[nc*4+2+cc]-hn,col, s1[1],i1[1],s2v[1],i2[1]);
            }
        }
        __syncthreads();
        issue_chunk(8+t,smb,tid);
    }
    // merge top-2 across ti lanes
    #pragma unroll
    for(int off=1;off<=2;off<<=1){
        #pragma unroll
        for(int s=0;s<2;s++){
            float os1=__shfl_xor_sync(0xffffffffu,s1[s],off);
            int   oi1=__shfl_xor_sync(0xffffffffu,i1[s],off);
            float os2=__shfl_xor_sync(0xffffffffu,s2v[s],off);
            int   oi2=__shfl_xor_sync(0xffffffffu,i2[s],off);
            top2ins(os1,oi1,s1[s],i1[s],s2v[s],i2[s]);
            top2ins(os2,oi2,s1[s],i1[s],s2v[s],i2[s]);
        }
    }
    // exact fp32 rescore of top-2 (all 4 ti lanes redundantly -> all know cw)
    float lsum=0.f;
    #pragma unroll
    for(int s=0;s<2;s++){
        int row=r0+s*8;
        const float* z=&zbuf[row*68];
        int ca=i1[s], cb=i2[s];
        float da=0.f,db=0.f;
        #pragma unroll 4
        for(int q=0;q<16;q++){
            float4 v1=__ldg((const float4*)&CB[(long)ca*64+q*4]);
            float4 v2=__ldg((const float4*)&CB[(long)cb*64+q*4]);
            float4 zv=*(const float4*)(z+q*4);
            da=fmaf(v1.x-zv.x,v1.x-zv.x,da); da=fmaf(v1.y-zv.y,v1.y-zv.y,da);
            da=fmaf(v1.z-zv.z,v1.z-zv.z,da); da=fmaf(v1.w-zv.w,v1.w-zv.w,da);
            db=fmaf(v2.x-zv.x,v2.x-zv.x,db); db=fmaf(v2.y-zv.y,v2.y-zv.y,db);
            db=fmaf(v2.z-zv.z,v2.z-zv.z,db); db=fmaf(v2.w-zv.w,v2.w-zv.w,db);
        }
        int cw; float dw;
        if(da<db||(da==db&&ca<cb)){ cw=ca; dw=da; } else { cw=cb; dw=db; }
        if(ti==0){ atomicAdd(&g_hist[cw],1); lsum+=dw; }
        // write q fp16 plane: this lane covers cols [ti*16, ti*16+16)
        #pragma unroll
        for(int q=0;q<4;q++){
            float4 v=__ldg((const float4*)&CB[(long)cw*64+ti*16+q*4]);
            *(u32*)(sa0h+row*72+ti*16+q*4)  =hpk(__float2half_rn(v.x),__float2half_rn(v.y));
            *(u32*)(sa0h+row*72+ti*16+q*4+2)=hpk(__float2half_rn(v.z),__float2half_rn(v.w));
        }
    }
    // ===== dec1 (K=64, 2-product, N=128) =====
    float c1[64];
    #pragma unroll
    for(int j=0;j<64;j++) c1[j]=0.f;
    pipe_wait(14);
    mma2<16>(sa0h+r0w*72,(const hf*)(sm+SBH0),(const hf*)(sm+SBL0),c1,lane);
    __syncthreads();
    issue_chunk(16,smb,tid);
    // d1 = relu(+db1) -> single fp16 plane SA0H(0-63)/SA1H(64-127)
    #pragma unroll
    for(int nc=0;nc<16;nc++){
        int c=nc*8+2*ti;
        float b0=__ldg(&DB1[c]), b1=__ldg(&DB1[c+1]);
        float v0=fmaxf(c1[nc*4+0]+b0,0.f), v1=fmaxf(c1[nc*4+1]+b1,0.f);
        float v2=fmaxf(c1[nc*4+2]+b0,0.f), v3=fmaxf(c1[nc*4+3]+b1,0.f);
        int off=c&63; hf* dh=(c<64)?sa0h:sa1h;
        *(u32*)(dh+r0*72+off)=hpk(__float2half_rn(v0),__float2half_rn(v1));
        *(u32*)(dh+(r0+8)*72+off)=hpk(__float2half_rn(v2),__float2half_rn(v3));
    }
    // ===== dec2 (2 N-halves x 2 K-chunks, 2-product) + dec3 partials =====
    float part[2][9];
    #pragma unroll
    for(int s=0;s<2;s++)
        #pragma unroll
        for(int j=0;j<9;j++) part[s][j]=0.f;
    for(int nh=0;nh<2;nh++){
        float c2[64];
        #pragma unroll
        for(int j=0;j<64;j++) c2[j]=0.f;
        for(int kc=0;kc<2;kc++){
            int ci=15+nh*2+kc;
            pipe_wait(ci);
            const hf* ah=(kc?sa1h:sa0h)+r0w*72;
            mma2<16>(ah,(const hf*)(sm+((ci&1)?SBH1:SBH0)),(const hf*)(sm+((ci&1)?SBL1:SBL0)),c2,lane);
            __syncthreads();
            issue_chunk(ci+2,smb,tid);
        }
        #pragma unroll
        for(int nc=0;nc<16;nc++){
            #pragma unroll
            for(int cc=0;cc<2;cc++){
                int c=nh*128+nc*8+2*ti+cc;
                float b=__ldg(&DB2[c]);
                float v0=fmaxf(c2[nc*4+cc]+b,0.f);
                float v1=fmaxf(c2[nc*4+2+cc]+b,0.f);
                #pragma unroll
                for(int j=0;j<9;j++){
                    float w=w3s[j*256+c];
                    part[0][j]=fmaf(v0,w,part[0][j]);
                    part[1][j]=fmaf(v1,w,part[1][j]);
                }
            }
        }
    }
    #pragma unroll
    for(int off=1;off<=2;off<<=1)
        #pragma unroll
        for(int s=0;s<2;s++)
            #pragma unroll
            for(int j=0;j<9;j++) part[s][j]+=__shfl_xor_sync(0xffffffffu,part[s][j],off);
    if(ti==0){
        #pragma unroll
        for(int s=0;s<2;s++){
            long row=row0+r0+s*8;
            #pragma unroll
            for(int j=0;j<9;j++) out[row*9+j]=part[s][j]+__ldg(&DB3[j]);
        }
    }
    // block mse partial
    #pragma unroll
    for(int o=16;o;o>>=1) lsum+=__shfl_xor_sync(0xffffffffu,lsum,o);
    if(lane==0) warr[warp]=lsum;
    __syncthreads();
    if(tid==0){
        float s=0.f;
        #pragma unroll
        for(int w=0;w<8;w++) s+=warr[w];
        g_msep[blockIdx.x]=s;
    }
}

// ---------------- finalize ----------------
__global__ void k_final(float* __restrict__ out){
    __shared__ double sd[1024];
    __shared__ double mt;
    int tid=threadIdx.x;
    sd[tid]=(double)g_msep[tid]+(double)g_msep[tid+1024];
    __syncthreads();
    for(int o=512;o;o>>=1){ if(tid<o) sd[tid]+=sd[tid+o]; __syncthreads(); }
    if(tid==0) mt=sd[0];
    __syncthreads();
    float p=(float)g_hist[tid]/262144.0f;
    sd[tid]=(double)(p*logf(p+1e-10f));
    __syncthreads();
    for(int o=512;o;o>>=1){ if(tid<o) sd[tid]+=sd[tid+o]; __syncthreads(); }
    if(tid==0){
        float mse=(float)(mt/(262144.0*64.0));
        out[262144*9+0]=1.25f*mse;
        out[262144*9+1]=expf(-(float)sd[0]);
    }
}

// ---------------------------------------------------------------------------
extern "C" void kernel_launch(void* const* d_in, const int* in_sizes, int n_in,
                              void* d_out, int out_size){
    const float* x  =(const float*)d_in[0];
    const float* ew1=(const float*)d_in[1];  const float* eb1=(const float*)d_in[2];
    const float* ew2=(const float*)d_in[3];  const float* eb2=(const float*)d_in[4];
    const float* ew3=(const float*)d_in[5];  const float* eb3=(const float*)d_in[6];
    const float* dw1=(const float*)d_in[7];  const float* db1=(const float*)d_in[8];
    const float* dw2=(const float*)d_in[9];  const float* db2=(const float*)d_in[10];
    const float* dw3=(const float*)d_in[11]; const float* db3=(const float*)d_in[12];
    const float* cb =(const float*)d_in[13];
    float* out=(float*)d_out;

    cudaFuncSetAttribute(k_main, cudaFuncAttributeMaxDynamicSharedMemorySize, SMTOT);

    k_prep<<<256,256>>>(ew2, ew3, dw1, dw2, cb);
    k_main<<<GRD,256,SMTOT>>>(x, ew1, eb1, eb2, eb3, cb, db1, db2, dw3, db3, out);
    k_final<<<1,1024>>>(out);
}

// round 11
// speedup vs baseline: 2.5931x; 1.0184x over previous
#include <cuda_runtime.h>
#include <cuda_fp16.h>
#include <math.h>

#define NRR 262144
#define GRD 2048
typedef unsigned int u32;
typedef __half hf;

// ---- static scratch (weights/codebook split planes only) ----
__device__ hf g_w2h[128*256], g_w2l[128*256];
__device__ hf g_w3h[64*128],  g_w3l[64*128];
__device__ hf g_d1h[128*64],  g_d1l[128*64];
__device__ hf g_d2h[256*128], g_d2l[256*128];
__device__ hf g_cbh[1024*64], g_cbl[1024*64];
__device__ float g_hn[1024];
__device__ int   g_hist[1024];
__device__ float g_msep[GRD];

__device__ __forceinline__ void fsp(float v, hf&h, hf&l){ h=__float2half_rn(v); l=__float2half_rn(v-__half2float(h)); }
__device__ __forceinline__ u32 hpk(hf a, hf b){ return (u32)__half_as_ushort(a) | ((u32)__half_as_ushort(b)<<16); }
__device__ __forceinline__ u32 smem_u32(const void* p){
    u32 a; asm("{ .reg .u64 t; cvta.to.shared.u64 t, %1; cvt.u32.u64 %0, t; }":"=r"(a):"l"(p)); return a;
}

#define MMA4(c,a0,a1,a2,a3,b0,b1) \
  asm volatile("mma.sync.aligned.m16n8k16.row.col.f32.f16.f16.f32 {%0,%1,%2,%3},{%4,%5,%6,%7},{%8,%9},{%0,%1,%2,%3};" \
    : "+f"((c)[0]),"+f"((c)[1]),"+f"((c)[2]),"+f"((c)[3]) \
    : "r"(a0),"r"(a1),"r"(a2),"r"(a3),"r"(b0),"r"(b1))

__device__ __forceinline__ void ldsm4(u32&r0,u32&r1,u32&r2,u32&r3,u32 addr){
    asm volatile("ldmatrix.sync.aligned.m8n8.x4.shared.b16 {%0,%1,%2,%3}, [%4];"
        :"=r"(r0),"=r"(r1),"=r"(r2),"=r"(r3):"r"(addr));
}

// Split GEMM over K=64 chunk via ldmatrix fragments.
// sAh/sAl: byte smem addr of this warp's 16-row A block (stride 72 halves).
// sBh/sBl: byte smem addr of B tile (NC*8 rows x 64 k, stride 72 halves).
// ALO=true adds the A-lo product (3-product); else 2-product.
template<int NC, bool ALO>
__device__ __forceinline__ void mmaN(u32 sAh, u32 sAl, u32 sBh, u32 sBl,
                                     float* cc, int lane){
    int l16 = lane & 15;
    u32 aOff = (u32)(l16*144 + (lane>>4)*16);          // row*144B + kHi*16B
    int q = lane>>3, rr = lane&7;
    u32 bOff = (u32)(((q>>1)*8 + rr)*144 + (q&1)*16);  // pair-row*144B + kHi*16B
    #pragma unroll
    for(int ks=0;ks<4;ks++){
        u32 kB = (u32)(ks*32);                         // 16 halves = 32 bytes
        u32 ah0,ah1,ah2,ah3, al0,al1,al2,al3;
        ldsm4(ah0,ah1,ah2,ah3, sAh + aOff + kB);
        if(ALO) ldsm4(al0,al1,al2,al3, sAl + aOff + kB);
        #pragma unroll
        for(int np=0;np<NC/2;np++){
            u32 bb = sBh + bOff + kB + (u32)(np*2304); // 16 rows * 144B
            u32 bh0,bh1,bh2,bh3, bl0,bl1,bl2,bl3;
            ldsm4(bh0,bh1,bh2,bh3, bb);
            ldsm4(bl0,bl1,bl2,bl3, (sBl - sBh) + bb);
            float* c0=cc+np*8; float* c1=cc+np*8+4;
            MMA4(c0,ah0,ah1,ah2,ah3,bh0,bh1);
            MMA4(c0,ah0,ah1,ah2,ah3,bl0,bl1);
            if(ALO) MMA4(c0,al0,al1,al2,al3,bh0,bh1);
            MMA4(c1,ah0,ah1,ah2,ah3,bh2,bh3);
            MMA4(c1,ah0,ah1,ah2,ah3,bl2,bl3);
            if(ALO) MMA4(c1,al0,al1,al2,al3,bh2,bh3);
        }
    }
}

__device__ __forceinline__ void top2ins(float s,int i,float&s1,int&i1,float&s2,int&i2){
    if(s>s1||(s==s1&&i<i1)){ s2=s1;i2=i1;s1=s;i1=i; }
    else if(s>s2||(s==s2&&i<i2)){ s2=s;i2=i; }
}

// smem byte offsets
#define SA0H 0
#define SA0L 18432
#define SA1H 36864
#define SA1L 55296
#define SBH0 73728
#define SBL0 92160
#define SBH1 110592
#define SBL1 129024
#define ZB   147456
#define W3S  182272
#define SMTOT 191488

// B-chunk schedule: 0-3 w2 | 4-5 w3 | 6-13 cb | 14 d1 | 15-18 d2
__device__ __forceinline__ void issue_chunk(int ci, u32 smb, int tid){
    if(ci>18) return;
    u32 dh = smb + ((ci&1)?SBH1:SBH0);
    u32 dl = smb + ((ci&1)?SBL1:SBL0);
    const hf *gh,*gl; long r0=0; int gs,ko,nr=128;
    if(ci<4){ gh=g_w2h; gl=g_w2l; gs=256; ko=ci*64; }
    else if(ci<6){ gh=g_w3h; gl=g_w3l; gs=128; ko=(ci-4)*64; nr=64; }
    else if(ci<14){ gh=g_cbh; gl=g_cbl; gs=64; ko=0; r0=(long)(ci-6)*128; }
    else if(ci==14){ gh=g_d1h; gl=g_d1l; gs=64; ko=0; }
    else { int t=ci-15; gh=g_d2h; gl=g_d2l; gs=128; r0=(long)(t>>1)*128; ko=(t&1)*64; }
    for(int i=tid;i<nr*8;i+=256){
        int r=i>>3, s=i&7;
        const hf* src=gh+(r0+r)*(long)gs+ko+s*8;
        asm volatile("cp.async.ca.shared.global [%0], [%1], 16;"::"r"(dh+(u32)(r*144+s*16)),"l"(src):"memory");
    }
    for(int i=tid;i<nr*8;i+=256){
        int r=i>>3, s=i&7;
        const hf* src=gl+(r0+r)*(long)gs+ko+s*8;
        asm volatile("cp.async.ca.shared.global [%0], [%1], 16;"::"r"(dl+(u32)(r*144+s*16)),"l"(src):"memory");
    }
    asm volatile("cp.async.commit_group;":::"memory");
}
__device__ __forceinline__ void pipe_wait(int ci){
    if(ci<18) asm volatile("cp.async.wait_group 1;":::"memory");
    else      asm volatile("cp.async.wait_group 0;":::"memory");
    __syncthreads();
}

// ---------------- prep ----------------
__global__ void k_prep(const float* __restrict__ w2, const float* __restrict__ w3,
                       const float* __restrict__ d1, const float* __restrict__ d2,
                       const float* __restrict__ cb){
    int i=blockIdx.x*256+threadIdx.x;
    if(i<128*256) fsp(w2[i],g_w2h[i],g_w2l[i]);
    if(i<64*128)  fsp(w3[i],g_w3h[i],g_w3l[i]);
    if(i<128*64)  fsp(d1[i],g_d1h[i],g_d1l[i]);
    if(i<256*128) fsp(d2[i],g_d2h[i],g_d2l[i]);
    if(i<1024*64) fsp(cb[i],g_cbh[i],g_cbl[i]);
    if(i<1024){
        float s=0.f;
        #pragma unroll 8
        for(int d=0;d<64;d++){ float v=cb[i*64+d]; s=fmaf(v,v,s); }
        g_hn[i]=0.5f*s; g_hist[i]=0;
    }
}

// ---------------- fused everything ----------------
__global__ __launch_bounds__(256,1)
void k_main(const float* __restrict__ X,  const float* __restrict__ W1,
            const float* __restrict__ B1, const float* __restrict__ B2,
            const float* __restrict__ B3e,const float* __restrict__ CB,
            const float* __restrict__ DB1,const float* __restrict__ DB2,
            const float* __restrict__ W3d,const float* __restrict__ DB3,
            float* __restrict__ out){
    extern __shared__ char sm[];
    hf* sa0h=(hf*)(sm+SA0H); hf* sa0l=(hf*)(sm+SA0L);
    hf* sa1h=(hf*)(sm+SA1H); hf* sa1l=(hf*)(sm+SA1L);
    float* zbuf=(float*)(sm+ZB);       // 128*68 fp32, overlays xs/w1s after enc2
    float* xs  =(float*)(sm+ZB);       // 128*12
    float* w1s =(float*)(sm+ZB+6144);  // 256*9
    float* w3s =(float*)(sm+W3S);      // 9*256
    __shared__ float warr[8];
    u32 smb=smem_u32(sm);
    int tid=threadIdx.x, warp=tid>>5, lane=tid&31;
    int gi=lane>>2, ti=lane&3, r0w=warp*16, r0=r0w+gi;
    u32 aW=(u32)(r0w*144);
    long row0=(long)blockIdx.x*128;

    issue_chunk(0,smb,tid);
    issue_chunk(1,smb,tid);
    for(int i=tid;i<128*9;i+=256){ int r=i/9,k=i-r*9; xs[r*12+k]=X[row0*9+i]; }
    for(int i=tid;i<256*9;i+=256) w1s[i]=W1[i];
    for(int i=tid;i<9*256;i+=256) w3s[i]=W3d[i];
    __syncthreads();

    // ===== enc2 (K=256, 4 chunks; enc1 computed on the fly, 3-product) =====
    float acc[64];
    #pragma unroll
    for(int j=0;j<64;j++) acc[j]=0.f;
    for(int ch=0;ch<4;ch++){
        for(int p=tid;p<128*32;p+=256){
            int r=p>>5, cp=p&31, c0=ch*64+2*cp;
            float a0=__ldg(&B1[c0]), a1=__ldg(&B1[c0+1]);
            #pragma unroll
            for(int k=0;k<9;k++){ float xv=xs[r*12+k]; a0=fmaf(xv,w1s[c0*9+k],a0); a1=fmaf(xv,w1s[(c0+1)*9+k],a1); }
            a0=fmaxf(a0,0.f); a1=fmaxf(a1,0.f);
            hf h0,l0,h1,l1; fsp(a0,h0,l0); fsp(a1,h1,l1);
            *(u32*)(sa0h+r*72+2*cp)=hpk(h0,h1);
            *(u32*)(sa0l+r*72+2*cp)=hpk(l0,l1);
        }
        pipe_wait(ch);
        mmaN<16,true>(smb+SA0H+aW, smb+SA0L+aW,
                      smb+((ch&1)?SBH1:SBH0), smb+((ch&1)?SBL1:SBL0), acc, lane);
        __syncthreads();
        issue_chunk(ch+2,smb,tid);
    }
    // h2 = relu(acc+b2) -> split planes SA0(0-63)/SA1(64-127)
    #pragma unroll
    for(int nc=0;nc<16;nc++){
        int c=nc*8+2*ti;
        float b0=__ldg(&B2[c]), b1=__ldg(&B2[c+1]);
        float v0=fmaxf(acc[nc*4+0]+b0,0.f), v1=fmaxf(acc[nc*4+1]+b1,0.f);
        float v2=fmaxf(acc[nc*4+2]+b0,0.f), v3=fmaxf(acc[nc*4+3]+b1,0.f);
        int off=c&63; hf* dh=(c<64)?sa0h:sa1h; hf* dl=(c<64)?sa0l:sa1l;
        hf h0,l0,h1,l1;
        fsp(v0,h0,l0); fsp(v1,h1,l1);
        *(u32*)(dh+r0*72+off)=hpk(h0,h1); *(u32*)(dl+r0*72+off)=hpk(l0,l1);
        fsp(v2,h0,l0); fsp(v3,h1,l1);
        *(u32*)(dh+(r0+8)*72+off)=hpk(h0,h1); *(u32*)(dl+(r0+8)*72+off)=hpk(l0,l1);
    }
    // ===== enc3 (K=128, 2 chunks, 3-product, N=64) =====
    float c3[32];
    #pragma unroll
    for(int j=0;j<32;j++) c3[j]=0.f;
    for(int ch=0;ch<2;ch++){
        pipe_wait(4+ch);
        u32 ah=smb+(ch?SA1H:SA0H)+aW, al=smb+(ch?SA1L:SA0L)+aW;
        mmaN<8,true>(ah,al,smb+(((4+ch)&1)?SBH1:SBH0),smb+(((4+ch)&1)?SBL1:SBL0),c3,lane);
        __syncthreads();
        issue_chunk(6+ch,smb,tid);
    }
    // z -> zbuf fp32 + fp16 plane in SA0H
    #pragma unroll
    for(int nc=0;nc<8;nc++){
        int c=nc*8+2*ti;
        float b0=__ldg(&B3e[c]), b1=__ldg(&B3e[c+1]);
        float z00=c3[nc*4+0]+b0, z01=c3[nc*4+1]+b1;
        float z10=c3[nc*4+2]+b0, z11=c3[nc*4+3]+b1;
        zbuf[r0*68+c]=z00; zbuf[r0*68+c+1]=z01;
        zbuf[(r0+8)*68+c]=z10; zbuf[(r0+8)*68+c+1]=z11;
        *(u32*)(sa0h+r0*72+c)=hpk(__float2half_rn(z00),__float2half_rn(z01));
        *(u32*)(sa0h+(r0+8)*72+c)=hpk(__float2half_rn(z10),__float2half_rn(z11));
    }
    // ===== VQ scan (2-product, 8 code tiles of 128) =====
    float s1[2]={-3.4e38f,-3.4e38f}, s2v[2]={-3.4e38f,-3.4e38f};
    int   i1[2]={0,0}, i2[2]={0,0};
    for(int t=0;t<8;t++){
        pipe_wait(6+t);
        float cv[64];
        #pragma unroll
        for(int j=0;j<64;j++) cv[j]=0.f;
        mmaN<16,false>(smb+SA0H+aW, 0u,
                       smb+(((6+t)&1)?SBH1:SBH0), smb+(((6+t)&1)?SBL1:SBL0), cv, lane);
        #pragma unroll
        for(int nc=0;nc<16;nc++){
            #pragma unroll
            for(int cc=0;cc<2;cc++){
                int col=t*128+nc*8+2*ti+cc;
                float hn=__ldg(&g_hn[col]);
                top2ins(cv[nc*4+cc]-hn,  col, s1[0],i1[0],s2v[0],i2[0]);
                top2ins(cv[nc*4+2+cc]-hn,col, s1[1],i1[1],s2v[1],i2[1]);
            }
        }
        __syncthreads();
        issue_chunk(8+t,smb,tid);
    }
    // merge top-2 across ti lanes
    #pragma unroll
    for(int off=1;off<=2;off<<=1){
        #pragma unroll
        for(int s=0;s<2;s++){
            float os1=__shfl_xor_sync(0xffffffffu,s1[s],off);
            int   oi1=__shfl_xor_sync(0xffffffffu,i1[s],off);
            float os2=__shfl_xor_sync(0xffffffffu,s2v[s],off);
            int   oi2=__shfl_xor_sync(0xffffffffu,i2[s],off);
            top2ins(os1,oi1,s1[s],i1[s],s2v[s],i2[s]);
            top2ins(os2,oi2,s1[s],i1[s],s2v[s],i2[s]);
        }
    }
    // exact fp32 rescore of top-2 (all 4 ti lanes redundantly -> all know cw)
    float lsum=0.f;
    #pragma unroll
    for(int s=0;s<2;s++){
        int row=r0+s*8;
        const float* z=&zbuf[row*68];
        int ca=i1[s], cb=i2[s];
        float da=0.f,db=0.f;
        #pragma unroll 4
        for(int q=0;q<16;q++){
            float4 v1=__ldg((const float4*)&CB[(long)ca*64+q*4]);
            float4 v2=__ldg((const float4*)&CB[(long)cb*64+q*4]);
            float4 zv=*(const float4*)(z+q*4);
            da=fmaf(v1.x-zv.x,v1.x-zv.x,da); da=fmaf(v1.y-zv.y,v1.y-zv.y,da);
            da=fmaf(v1.z-zv.z,v1.z-zv.z,da); da=fmaf(v1.w-zv.w,v1.w-zv.w,da);
            db=fmaf(v2.x-zv.x,v2.x-zv.x,db); db=fmaf(v2.y-zv.y,v2.y-zv.y,db);
            db=fmaf(v2.z-zv.z,v2.z-zv.z,db); db=fmaf(v2.w-zv.w,v2.w-zv.w,db);
        }
        int cw; float dw;
        if(da<db||(da==db&&ca<cb)){ cw=ca; dw=da; } else { cw=cb; dw=db; }
        if(ti==0){ atomicAdd(&g_hist[cw],1); lsum+=dw; }
        // write q fp16 plane: this lane covers cols [ti*16, ti*16+16)
        #pragma unroll
        for(int q=0;q<4;q++){
            float4 v=__ldg((const float4*)&CB[(long)cw*64+ti*16+q*4]);
            *(u32*)(sa0h+row*72+ti*16+q*4)  =hpk(__float2half_rn(v.x),__float2half_rn(v.y));
            *(u32*)(sa0h+row*72+ti*16+q*4+2)=hpk(__float2half_rn(v.z),__float2half_rn(v.w));
        }
    }
    // ===== dec1 (K=64, 2-product, N=128) =====
    float c1[64];
    #pragma unroll
    for(int j=0;j<64;j++) c1[j]=0.f;
    pipe_wait(14);
    mmaN<16,false>(smb+SA0H+aW, 0u, smb+SBH0, smb+SBL0, c1, lane);
    __syncthreads();
    issue_chunk(16,smb,tid);
    // d1 = relu(+db1) -> single fp16 plane SA0H(0-63)/SA1H(64-127)
    #pragma unroll
    for(int nc=0;nc<16;nc++){
        int c=nc*8+2*ti;
        float b0=__ldg(&DB1[c]), b1=__ldg(&DB1[c+1]);
        float v0=fmaxf(c1[nc*4+0]+b0,0.f), v1=fmaxf(c1[nc*4+1]+b1,0.f);
        float v2=fmaxf(c1[nc*4+2]+b0,0.f), v3=fmaxf(c1[nc*4+3]+b1,0.f);
        int off=c&63; hf* dh=(c<64)?sa0h:sa1h;
        *(u32*)(dh+r0*72+off)=hpk(__float2half_rn(v0),__float2half_rn(v1));
        *(u32*)(dh+(r0+8)*72+off)=hpk(__float2half_rn(v2),__float2half_rn(v3));
    }
    // ===== dec2 (2 N-halves x 2 K-chunks, 2-product) + dec3 partials =====
    float part[2][9];
    #pragma unroll
    for(int s=0;s<2;s++)
        #pragma unroll
        for(int j=0;j<9;j++) part[s][j]=0.f;
    for(int nh=0;nh<2;nh++){
        float c2[64];
        #pragma unroll
        for(int j=0;j<64;j++) c2[j]=0.f;
        for(int kc=0;kc<2;kc++){
            int ci=15+nh*2+kc;
            pipe_wait(ci);
            u32 ah=smb+(kc?SA1H:SA0H)+aW;
            mmaN<16,false>(ah, 0u, smb+((ci&1)?SBH1:SBH0), smb+((ci&1)?SBL1:SBL0), c2, lane);
            __syncthreads();
            issue_chunk(ci+2,smb,tid);
        }
        #pragma unroll
        for(int nc=0;nc<16;nc++){
            #pragma unroll
            for(int cc=0;cc<2;cc++){
                int c=nh*128+nc*8+2*ti+cc;
                float b=__ldg(&DB2[c]);
                float v0=fmaxf(c2[nc*4+cc]+b,0.f);
                float v1=fmaxf(c2[nc*4+2+cc]+b,0.f);
                #pragma unroll
                for(int j=0;j<9;j++){
                    float w=w3s[j*256+c];
                    part[0][j]=fmaf(v0,w,part[0][j]);
                    part[1][j]=fmaf(v1,w,part[1][j]);
                }
            }
        }
    }
    #pragma unroll
    for(int off=1;off<=2;off<<=1)
        #pragma unroll
        for(int s=0;s<2;s++)
            #pragma unroll
            for(int j=0;j<9;j++) part[s][j]+=__shfl_xor_sync(0xffffffffu,part[s][j],off);
    if(ti==0){
        #pragma unroll
        for(int s=0;s<2;s++){
            long row=row0+r0+s*8;
            #pragma unroll
            for(int j=0;j<9;j++) out[row*9+j]=part[s][j]+__ldg(&DB3[j]);
        }
    }
    // block mse partial
    #pragma unroll
    for(int o=16;o;o>>=1) lsum+=__shfl_xor_sync(0xffffffffu,lsum,o);
    if(lane==0) warr[warp]=lsum;
    __syncthreads();
    if(tid==0){
        float s=0.f;
        #pragma unroll
        for(int w=0;w<8;w++) s+=warr[w];
        g_msep[blockIdx.x]=s;
    }
}

// ---------------- finalize ----------------
__global__ void k_final(float* __restrict__ out){
    __shared__ double sd[1024];
    __shared__ double mt;
    int tid=threadIdx.x;
    sd[tid]=(double)g_msep[tid]+(double)g_msep[tid+1024];
    __syncthreads();
    for(int o=512;o;o>>=1){ if(tid<o) sd[tid]+=sd[tid+o]; __syncthreads(); }
    if(tid==0) mt=sd[0];
    __syncthreads();
    float p=(float)g_hist[tid]/262144.0f;
    sd[tid]=(double)(p*logf(p+1e-10f));
    __syncthreads();
    for(int o=512;o;o>>=1){ if(tid<o) sd[tid]+=sd[tid+o]; __syncthreads(); }
    if(tid==0){
        float mse=(float)(mt/(262144.0*64.0));
        out[262144*9+0]=1.25f*mse;
        out[262144*9+1]=expf(-(float)sd[0]);
    }
}

// ---------------------------------------------------------------------------
extern "C" void kernel_launch(void* const* d_in, const int* in_sizes, int n_in,
                              void* d_out, int out_size){
    const float* x  =(const float*)d_in[0];
    const float* ew1=(const float*)d_in[1];  const float* eb1=(const float*)d_in[2];
    const float* ew2=(const float*)d_in[3];  const float* eb2=(const float*)d_in[4];
    const float* ew3=(const float*)d_in[5];  const float* eb3=(const float*)d_in[6];
    const float* dw1=(const float*)d_in[7];  const float* db1=(const float*)d_in[8];
    const float* dw2=(const float*)d_in[9];  const float* db2=(const float*)d_in[10];
    const float* dw3=(const float*)d_in[11]; const float* db3=(const float*)d_in[12];
    const float* cb =(const float*)d_in[13];
    float* out=(float*)d_out;

    cudaFuncSetAttribute(k_main, cudaFuncAttributeMaxDynamicSharedMemorySize, SMTOT);

    k_prep<<<256,256>>>(ew2, ew3, dw1, dw2, cb);
    k_main<<<GRD,256,SMTOT>>>(x, ew1, eb1, eb2, eb3, cb, db1, db2, dw3, db3, out);
    k_final<<<1,1024>>>(out);
}

// round 12
// speedup vs baseline: 4.1322x; 1.5935x over previous
#include <cuda_runtime.h>
#include <cuda_fp16.h>
#include <math.h>

#define NRR 262144
#define GRD 2048
typedef unsigned int u32;
typedef __half hf;

// ---- static scratch (weights/codebook split planes only) ----
__device__ hf g_w2h[128*256], g_w2l[128*256];
__device__ hf g_w3h[64*128],  g_w3l[64*128];
__device__ hf g_d1h[128*64];
__device__ hf g_d2h[256*128];
__device__ hf g_cbh[1024*64];
__device__ float g_hn[1024];
__device__ int   g_hist[1024];
__device__ float g_msep[GRD];

__device__ __forceinline__ void fsp(float v, hf&h, hf&l){ h=__float2half_rn(v); l=__float2half_rn(v-__half2float(h)); }
__device__ __forceinline__ u32 hpk(hf a, hf b){ return (u32)__half_as_ushort(a) | ((u32)__half_as_ushort(b)<<16); }
__device__ __forceinline__ u32 smem_u32(const void* p){
    u32 a; asm("{ .reg .u64 t; cvta.to.shared.u64 t, %1; cvt.u32.u64 %0, t; }":"=r"(a):"l"(p)); return a;
}

#define MMA4(c,a0,a1,a2,a3,b0,b1) \
  asm volatile("mma.sync.aligned.m16n8k16.row.col.f32.f16.f16.f32 {%0,%1,%2,%3},{%4,%5,%6,%7},{%8,%9},{%0,%1,%2,%3};" \
    : "+f"((c)[0]),"+f"((c)[1]),"+f"((c)[2]),"+f"((c)[3]) \
    : "r"(a0),"r"(a1),"r"(a2),"r"(a3),"r"(b0),"r"(b1))

__device__ __forceinline__ void ldsm4(u32&r0,u32&r1,u32&r2,u32&r3,u32 addr){
    asm volatile("ldmatrix.sync.aligned.m8n8.x4.shared.b16 {%0,%1,%2,%3}, [%4];"
        :"=r"(r0),"=r"(r1),"=r"(r2),"=r"(r3):"r"(addr));
}

// Split GEMM over K=64 chunk via ldmatrix fragments.
// ALO: add A-lo x B-hi product.  BLO: add A-hi x B-lo product.
template<int NC, bool ALO, bool BLO>
__device__ __forceinline__ void mmaN(u32 sAh, u32 sAl, u32 sBh, u32 sBl,
                                     float* cc, int lane){
    int l16 = lane & 15;
    u32 aOff = (u32)(l16*144 + (lane>>4)*16);
    int q = lane>>3, rr = lane&7;
    u32 bOff = (u32)(((q>>1)*8 + rr)*144 + (q&1)*16);
    #pragma unroll
    for(int ks=0;ks<4;ks++){
        u32 kB = (u32)(ks*32);
        u32 ah0,ah1,ah2,ah3, al0,al1,al2,al3;
        ldsm4(ah0,ah1,ah2,ah3, sAh + aOff + kB);
        if(ALO) ldsm4(al0,al1,al2,al3, sAl + aOff + kB);
        #pragma unroll
        for(int np=0;np<NC/2;np++){
            u32 bb = sBh + bOff + kB + (u32)(np*2304);
            u32 bh0,bh1,bh2,bh3, bl0,bl1,bl2,bl3;
            ldsm4(bh0,bh1,bh2,bh3, bb);
            if(BLO) ldsm4(bl0,bl1,bl2,bl3, (sBl - sBh) + bb);
            float* c0=cc+np*8; float* c1=cc+np*8+4;
            MMA4(c0,ah0,ah1,ah2,ah3,bh0,bh1);
            if(BLO) MMA4(c0,ah0,ah1,ah2,ah3,bl0,bl1);
            if(ALO) MMA4(c0,al0,al1,al2,al3,bh0,bh1);
            MMA4(c1,ah0,ah1,ah2,ah3,bh2,bh3);
            if(BLO) MMA4(c1,ah0,ah1,ah2,ah3,bl2,bl3);
            if(ALO) MMA4(c1,al0,al1,al2,al3,bh2,bh3);
        }
    }
}

// tie-aware (for cross-lane merge)
__device__ __forceinline__ void top2ins(float s,int i,float&s1,int&i1,float&s2,int&i2){
    if(s>s1||(s==s1&&i<i1)){ s2=s1;i2=i1;s1=s;i1=i; }
    else if(s>s2||(s==s2&&i<i2)){ s2=s;i2=i; }
}
// fast (per-thread ascending-index scan: strict > keeps first index)
__device__ __forceinline__ void top2f(float s,int i,float&s1,int&i1,float&s2,int&i2){
    if(s>s1){ s2=s1;i2=i1;s1=s;i1=i; }
    else if(s>s2){ s2=s;i2=i; }
}

// smem byte offsets
#define SA0H 0
#define SA0L 18432
#define SA1H 36864
#define SA1L 55296
#define SBH0 73728
#define SBL0 92160
#define SBH1 110592
#define SBL1 129024
#define ZB   147456
#define W3S  182272
#define HNS  191488
#define SMTOT 195584

// B-chunk schedule: 0-3 w2 | 4-5 w3 | 6-13 cb | 14 d1 | 15-18 d2
// chunks >=6 are single-product consumers: stage hi plane only.
__device__ __forceinline__ void issue_chunk(int ci, u32 smb, int tid){
    if(ci>18) return;
    u32 dh = smb + ((ci&1)?SBH1:SBH0);
    u32 dl = smb + ((ci&1)?SBL1:SBL0);
    const hf *gh,*gl=0; long r0=0; int gs,ko,nr=128;
    if(ci<4){ gh=g_w2h; gl=g_w2l; gs=256; ko=ci*64; }
    else if(ci<6){ gh=g_w3h; gl=g_w3l; gs=128; ko=(ci-4)*64; nr=64; }
    else if(ci<14){ gh=g_cbh; gs=64; ko=0; r0=(long)(ci-6)*128; }
    else if(ci==14){ gh=g_d1h; gs=64; ko=0; }
    else { int t=ci-15; gh=g_d2h; gs=128; r0=(long)(t>>1)*128; ko=(t&1)*64; }
    for(int i=tid;i<nr*8;i+=256){
        int r=i>>3, s=i&7;
        const hf* src=gh+(r0+r)*(long)gs+ko+s*8;
        asm volatile("cp.async.ca.shared.global [%0], [%1], 16;"::"r"(dh+(u32)(r*144+s*16)),"l"(src):"memory");
    }
    if(ci<6){
        for(int i=tid;i<nr*8;i+=256){
            int r=i>>3, s=i&7;
            const hf* src=gl+(r0+r)*(long)gs+ko+s*8;
            asm volatile("cp.async.ca.shared.global [%0], [%1], 16;"::"r"(dl+(u32)(r*144+s*16)),"l"(src):"memory");
        }
    }
    asm volatile("cp.async.commit_group;":::"memory");
}
__device__ __forceinline__ void pipe_wait(int ci){
    if(ci<18) asm volatile("cp.async.wait_group 1;":::"memory");
    else      asm volatile("cp.async.wait_group 0;":::"memory");
    __syncthreads();
}

// ---------------- prep ----------------
__global__ void k_prep(const float* __restrict__ w2, const float* __restrict__ w3,
                       const float* __restrict__ d1, const float* __restrict__ d2,
                       const float* __restrict__ cb){
    int i=blockIdx.x*256+threadIdx.x;
    if(i<128*256) fsp(w2[i],g_w2h[i],g_w2l[i]);
    if(i<64*128)  fsp(w3[i],g_w3h[i],g_w3l[i]);
    if(i<128*64)  g_d1h[i]=__float2half_rn(d1[i]);
    if(i<256*128) g_d2h[i]=__float2half_rn(d2[i]);
    if(i<1024*64) g_cbh[i]=__float2half_rn(cb[i]);
    if(i<1024){
        float s=0.f;
        #pragma unroll 8
        for(int d=0;d<64;d++){ float v=cb[i*64+d]; s=fmaf(v,v,s); }
        g_hn[i]=0.5f*s; g_hist[i]=0;
    }
}

// ---------------- fused everything ----------------
__global__ __launch_bounds__(256,1)
void k_main(const float* __restrict__ X,  const float* __restrict__ W1,
            const float* __restrict__ B1, const float* __restrict__ B2,
            const float* __restrict__ B3e,const float* __restrict__ CB,
            const float* __restrict__ DB1,const float* __restrict__ DB2,
            const float* __restrict__ W3d,const float* __restrict__ DB3,
            float* __restrict__ out){
    extern __shared__ char sm[];
    hf* sa0h=(hf*)(sm+SA0H); hf* sa0l=(hf*)(sm+SA0L);
    hf* sa1h=(hf*)(sm+SA1H); hf* sa1l=(hf*)(sm+SA1L);
    float* zbuf=(float*)(sm+ZB);       // 128*68 fp32, overlays xs/w1s after enc2
    float* xs  =(float*)(sm+ZB);       // 128*12
    float* w1s =(float*)(sm+ZB+6144);  // 256*9
    float* w3s =(float*)(sm+W3S);      // 9*256
    float* hns =(float*)(sm+HNS);      // 1024
    __shared__ float warr[8];
    u32 smb=smem_u32(sm);
    int tid=threadIdx.x, warp=tid>>5, lane=tid&31;
    int gi=lane>>2, ti=lane&3, r0w=warp*16, r0=r0w+gi;
    u32 aW=(u32)(r0w*144);
    long row0=(long)blockIdx.x*128;

    issue_chunk(0,smb,tid);
    issue_chunk(1,smb,tid);
    for(int i=tid;i<128*9;i+=256){ int r=i/9,k=i-r*9; xs[r*12+k]=X[row0*9+i]; }
    for(int i=tid;i<256*9;i+=256) w1s[i]=W1[i];
    for(int i=tid;i<9*256;i+=256) w3s[i]=W3d[i];
    for(int i=tid;i<1024;i+=256) hns[i]=g_hn[i];
    __syncthreads();

    // ===== enc2 (K=256, 4 chunks; enc1 computed on the fly, 3-product) =====
    float acc[64];
    #pragma unroll
    for(int j=0;j<64;j++) acc[j]=0.f;
    for(int ch=0;ch<4;ch++){
        for(int p=tid;p<128*32;p+=256){
            int r=p>>5, cp=p&31, c0=ch*64+2*cp;
            float a0=__ldg(&B1[c0]), a1=__ldg(&B1[c0+1]);
            #pragma unroll
            for(int k=0;k<9;k++){ float xv=xs[r*12+k]; a0=fmaf(xv,w1s[c0*9+k],a0); a1=fmaf(xv,w1s[(c0+1)*9+k],a1); }
            a0=fmaxf(a0,0.f); a1=fmaxf(a1,0.f);
            hf h0,l0,h1,l1; fsp(a0,h0,l0); fsp(a1,h1,l1);
            *(u32*)(sa0h+r*72+2*cp)=hpk(h0,h1);
            *(u32*)(sa0l+r*72+2*cp)=hpk(l0,l1);
        }
        pipe_wait(ch);
        mmaN<16,true,true>(smb+SA0H+aW, smb+SA0L+aW,
                      smb+((ch&1)?SBH1:SBH0), smb+((ch&1)?SBL1:SBL0), acc, lane);
        __syncthreads();
        issue_chunk(ch+2,smb,tid);
    }
    // h2 = relu(acc+b2) -> split planes SA0(0-63)/SA1(64-127)
    #pragma unroll
    for(int nc=0;nc<16;nc++){
        int c=nc*8+2*ti;
        float b0=__ldg(&B2[c]), b1=__ldg(&B2[c+1]);
        float v0=fmaxf(acc[nc*4+0]+b0,0.f), v1=fmaxf(acc[nc*4+1]+b1,0.f);
        float v2=fmaxf(acc[nc*4+2]+b0,0.f), v3=fmaxf(acc[nc*4+3]+b1,0.f);
        int off=c&63; hf* dh=(c<64)?sa0h:sa1h; hf* dl=(c<64)?sa0l:sa1l;
        hf h0,l0,h1,l1;
        fsp(v0,h0,l0); fsp(v1,h1,l1);
        *(u32*)(dh+r0*72+off)=hpk(h0,h1); *(u32*)(dl+r0*72+off)=hpk(l0,l1);
        fsp(v2,h0,l0); fsp(v3,h1,l1);
        *(u32*)(dh+(r0+8)*72+off)=hpk(h0,h1); *(u32*)(dl+(r0+8)*72+off)=hpk(l0,l1);
    }
    // ===== enc3 (K=128, 2 chunks, 3-product, N=64) =====
    float c3[32];
    #pragma unroll
    for(int j=0;j<32;j++) c3[j]=0.f;
    for(int ch=0;ch<2;ch++){
        pipe_wait(4+ch);
        u32 ah=smb+(ch?SA1H:SA0H)+aW, al=smb+(ch?SA1L:SA0L)+aW;
        mmaN<8,true,true>(ah,al,smb+(((4+ch)&1)?SBH1:SBH0),smb+(((4+ch)&1)?SBL1:SBL0),c3,lane);
        __syncthreads();
        issue_chunk(6+ch,smb,tid);
    }
    // z -> zbuf fp32 + fp16 plane in SA0H
    #pragma unroll
    for(int nc=0;nc<8;nc++){
        int c=nc*8+2*ti;
        float b0=__ldg(&B3e[c]), b1=__ldg(&B3e[c+1]);
        float z00=c3[nc*4+0]+b0, z01=c3[nc*4+1]+b1;
        float z10=c3[nc*4+2]+b0, z11=c3[nc*4+3]+b1;
        zbuf[r0*68+c]=z00; zbuf[r0*68+c+1]=z01;
        zbuf[(r0+8)*68+c]=z10; zbuf[(r0+8)*68+c+1]=z11;
        *(u32*)(sa0h+r0*72+c)=hpk(__float2half_rn(z00),__float2half_rn(z01));
        *(u32*)(sa0h+(r0+8)*72+c)=hpk(__float2half_rn(z10),__float2half_rn(z11));
    }
    // ===== VQ scan (1-product + exact top-2 rescore, 8 code tiles of 128) =====
    float s1[2]={-3.4e38f,-3.4e38f}, s2v[2]={-3.4e38f,-3.4e38f};
    int   i1[2]={0,0}, i2[2]={0,0};
    for(int t=0;t<8;t++){
        pipe_wait(6+t);
        float cv[64];
        #pragma unroll
        for(int j=0;j<64;j++) cv[j]=0.f;
        mmaN<16,false,false>(smb+SA0H+aW, 0u,
                       smb+(((6+t)&1)?SBH1:SBH0), 0u, cv, lane);
        #pragma unroll
        for(int nc=0;nc<16;nc++){
            #pragma unroll
            for(int cc=0;cc<2;cc++){
                int col=t*128+nc*8+2*ti+cc;
                float hn=hns[col];
                top2f(cv[nc*4+cc]-hn,  col, s1[0],i1[0],s2v[0],i2[0]);
                top2f(cv[nc*4+2+cc]-hn,col, s1[1],i1[1],s2v[1],i2[1]);
            }
        }
        __syncthreads();
        issue_chunk(8+t,smb,tid);
    }
    // merge top-2 across ti lanes (tie-aware)
    #pragma unroll
    for(int off=1;off<=2;off<<=1){
        #pragma unroll
        for(int s=0;s<2;s++){
            float os1=__shfl_xor_sync(0xffffffffu,s1[s],off);
            int   oi1=__shfl_xor_sync(0xffffffffu,i1[s],off);
            float os2=__shfl_xor_sync(0xffffffffu,s2v[s],off);
            int   oi2=__shfl_xor_sync(0xffffffffu,i2[s],off);
            top2ins(os1,oi1,s1[s],i1[s],s2v[s],i2[s]);
            top2ins(os2,oi2,s1[s],i1[s],s2v[s],i2[s]);
        }
    }
    // exact fp32 rescore of top-2 (all 4 ti lanes redundantly -> all know cw)
    float lsum=0.f;
    #pragma unroll
    for(int s=0;s<2;s++){
        int row=r0+s*8;
        const float* z=&zbuf[row*68];
        int ca=i1[s], cb=i2[s];
        float da=0.f,db=0.f;
        #pragma unroll 4
        for(int q=0;q<16;q++){
            float4 v1=__ldg((const float4*)&CB[(long)ca*64+q*4]);
            float4 v2=__ldg((const float4*)&CB[(long)cb*64+q*4]);
            float4 zv=*(const float4*)(z+q*4);
            da=fmaf(v1.x-zv.x,v1.x-zv.x,da); da=fmaf(v1.y-zv.y,v1.y-zv.y,da);
            da=fmaf(v1.z-zv.z,v1.z-zv.z,da); da=fmaf(v1.w-zv.w,v1.w-zv.w,da);
            db=fmaf(v2.x-zv.x,v2.x-zv.x,db); db=fmaf(v2.y-zv.y,v2.y-zv.y,db);
            db=fmaf(v2.z-zv.z,v2.z-zv.z,db); db=fmaf(v2.w-zv.w,v2.w-zv.w,db);
        }
        int cw; float dw;
        if(da<db||(da==db&&ca<cb)){ cw=ca; dw=da; } else { cw=cb; dw=db; }
        if(ti==0){ atomicAdd(&g_hist[cw],1); lsum+=dw; }
        // write q fp16 plane: this lane covers cols [ti*16, ti*16+16)
        #pragma unroll
        for(int q=0;q<4;q++){
            float4 v=__ldg((const float4*)&CB[(long)cw*64+ti*16+q*4]);
            *(u32*)(sa0h+row*72+ti*16+q*4)  =hpk(__float2half_rn(v.x),__float2half_rn(v.y));
            *(u32*)(sa0h+row*72+ti*16+q*4+2)=hpk(__float2half_rn(v.z),__float2half_rn(v.w));
        }
    }
    // ===== dec1 (K=64, 1-product, N=128) =====
    float c1[64];
    #pragma unroll
    for(int j=0;j<64;j++) c1[j]=0.f;
    pipe_wait(14);
    mmaN<16,false,false>(smb+SA0H+aW, 0u, smb+SBH0, 0u, c1, lane);
    __syncthreads();
    issue_chunk(16,smb,tid);
    // d1 = relu(+db1) -> single fp16 plane SA0H(0-63)/SA1H(64-127)
    #pragma unroll
    for(int nc=0;nc<16;nc++){
        int c=nc*8+2*ti;
        float b0=__ldg(&DB1[c]), b1=__ldg(&DB1[c+1]);
        float v0=fmaxf(c1[nc*4+0]+b0,0.f), v1=fmaxf(c1[nc*4+1]+b1,0.f);
        float v2=fmaxf(c1[nc*4+2]+b0,0.f), v3=fmaxf(c1[nc*4+3]+b1,0.f);
        int off=c&63; hf* dh=(c<64)?sa0h:sa1h;
        *(u32*)(dh+r0*72+off)=hpk(__float2half_rn(v0),__float2half_rn(v1));
        *(u32*)(dh+(r0+8)*72+off)=hpk(__float2half_rn(v2),__float2half_rn(v3));
    }
    // ===== dec2 (2 N-halves x 2 K-chunks, 1-product) + dec3 partials =====
    float part[2][9];
    #pragma unroll
    for(int s=0;s<2;s++)
        #pragma unroll
        for(int j=0;j<9;j++) part[s][j]=0.f;
    for(int nh=0;nh<2;nh++){
        float c2[64];
        #pragma unroll
        for(int j=0;j<64;j++) c2[j]=0.f;
        for(int kc=0;kc<2;kc++){
            int ci=15+nh*2+kc;
            pipe_wait(ci);
            u32 ah=smb+(kc?SA1H:SA0H)+aW;
            mmaN<16,false,false>(ah, 0u, smb+((ci&1)?SBH1:SBH0), 0u, c2, lane);
            __syncthreads();
            issue_chunk(ci+2,smb,tid);
        }
        #pragma unroll
        for(int nc=0;nc<16;nc++){
            #pragma unroll
            for(int cc=0;cc<2;cc++){
                int c=nh*128+nc*8+2*ti+cc;
                float b=__ldg(&DB2[c]);
                float v0=fmaxf(c2[nc*4+cc]+b,0.f);
                float v1=fmaxf(c2[nc*4+2+cc]+b,0.f);
                #pragma unroll
                for(int j=0;j<9;j++){
                    float w=w3s[j*256+c];
                    part[0][j]=fmaf(v0,w,part[0][j]);
                    part[1][j]=fmaf(v1,w,part[1][j]);
                }
            }
        }
    }
    #pragma unroll
    for(int off=1;off<=2;off<<=1)
        #pragma unroll
        for(int s=0;s<2;s++)
            #pragma unroll
            for(int j=0;j<9;j++) part[s][j]+=__shfl_xor_sync(0xffffffffu,part[s][j],off);
    if(ti==0){
        #pragma unroll
        for(int s=0;s<2;s++){
            long row=row0+r0+s*8;
            #pragma unroll
            for(int j=0;j<9;j++) out[row*9+j]=part[s][j]+__ldg(&DB3[j]);
        }
    }
    // block mse partial
    #pragma unroll
    for(int o=16;o;o>>=1) lsum+=__shfl_xor_sync(0xffffffffu,lsum,o);
    if(lane==0) warr[warp]=lsum;
    __syncthreads();
    if(tid==0){
        float s=0.f;
        #pragma unroll
        for(int w=0;w<8;w++) s+=warr[w];
        g_msep[blockIdx.x]=s;
    }
}

// ---------------- finalize ----------------
__global__ void k_final(float* __restrict__ out){
    __shared__ double sd[1024];
    __shared__ double mt;
    int tid=threadIdx.x;
    sd[tid]=(double)g_msep[tid]+(double)g_msep[tid+1024];
    __syncthreads();
    for(int o=512;o;o>>=1){ if(tid<o) sd[tid]+=sd[tid+o]; __syncthreads(); }
    if(tid==0) mt=sd[0];
    __syncthreads();
    float p=(float)g_hist[tid]/262144.0f;
    sd[tid]=(double)(p*logf(p+1e-10f));
    __syncthreads();
    for(int o=512;o;o>>=1){ if(tid<o) sd[tid]+=sd[tid+o]; __syncthreads(); }
    if(tid==0){
        float mse=(float)(mt/(262144.0*64.0));
        out[262144*9+0]=1.25f*mse;
        out[262144*9+1]=expf(-(float)sd[0]);
    }
}

// ---------------------------------------------------------------------------
extern "C" void kernel_launch(void* const* d_in, const int* in_sizes, int n_in,
                              void* d_out, int out_size){
    const float* x  =(const float*)d_in[0];
    const float* ew1=(const float*)d_in[1];  const float* eb1=(const float*)d_in[2];
    const float* ew2=(const float*)d_in[3];  const float* eb2=(const float*)d_in[4];
    const float* ew3=(const float*)d_in[5];  const float* eb3=(const float*)d_in[6];
    const float* dw1=(const float*)d_in[7];  const float* db1=(const float*)d_in[8];
    const float* dw2=(const float*)d_in[9];  const float* db2=(const float*)d_in[10];
    const float* dw3=(const float*)d_in[11]; const float* db3=(const float*)d_in[12];
    const float* cb =(const float*)d_in[13];
    float* out=(float*)d_out;

    cudaFuncSetAttribute(k_main, cudaFuncAttributeMaxDynamicSharedMemorySize, SMTOT);

    k_prep<<<256,256>>>(ew2, ew3, dw1, dw2, cb);
    k_main<<<GRD,256,SMTOT>>>(x, ew1, eb1, eb2, eb3, cb, db1, db2, dw3, db3, out);
    k_final<<<1,1024>>>(out);
}

// round 16
// speedup vs baseline: 4.6106x; 1.1158x over previous
#include <cuda_runtime.h>
#include <cuda_fp16.h>
#include <math.h>

#define NRR 262144
#define GRD 2048
typedef unsigned int u32;
typedef __half hf;

// ---- static scratch ----
__device__ hf g_w2h[128*256], g_w2l[128*256];
__device__ hf g_w3h[64*128],  g_w3l[64*128];
__device__ hf g_d1h[128*64];
__device__ hf g_d2h[256*128];
__device__ hf g_cbh[1024*64];
__device__ float g_hn[1024];
__device__ int   g_hist[1024];
__device__ float g_msep[GRD];

__device__ __forceinline__ void fsp(float v, hf&h, hf&l){ h=__float2half_rn(v); l=__float2half_rn(v-__half2float(h)); }
__device__ __forceinline__ u32 hpk(hf a, hf b){ return (u32)__half_as_ushort(a) | ((u32)__half_as_ushort(b)<<16); }
__device__ __forceinline__ u32 smem_u32(const void* p){
    u32 a; asm("{ .reg .u64 t; cvta.to.shared.u64 t, %1; cvt.u32.u64 %0, t; }":"=r"(a):"l"(p)); return a;
}

#define MMA4(c,a0,a1,a2,a3,b0,b1) \
  asm volatile("mma.sync.aligned.m16n8k16.row.col.f32.f16.f16.f32 {%0,%1,%2,%3},{%4,%5,%6,%7},{%8,%9},{%0,%1,%2,%3};" \
    : "+f"((c)[0]),"+f"((c)[1]),"+f"((c)[2]),"+f"((c)[3]) \
    : "r"(a0),"r"(a1),"r"(a2),"r"(a3),"r"(b0),"r"(b1))

__device__ __forceinline__ void ldsm4(u32&r0,u32&r1,u32&r2,u32&r3,u32 addr){
    asm volatile("ldmatrix.sync.aligned.m8n8.x4.shared.b16 {%0,%1,%2,%3}, [%4];"
        :"=r"(r0),"=r"(r1),"=r"(r2),"=r"(r3):"r"(addr));
}

// Split GEMM over K=64 chunk via ldmatrix fragments.
template<int NC, bool ALO, bool BLO>
__device__ __forceinline__ void mmaN(u32 sAh, u32 sAl, u32 sBh, u32 sBl,
                                     float* cc, int lane){
    int l16 = lane & 15;
    u32 aOff = (u32)(l16*144 + (lane>>4)*16);
    int q = lane>>3, rr = lane&7;
    u32 bOff = (u32)(((q>>1)*8 + rr)*144 + (q&1)*16);
    #pragma unroll
    for(int ks=0;ks<4;ks++){
        u32 kB = (u32)(ks*32);
        u32 ah0,ah1,ah2,ah3, al0,al1,al2,al3;
        ldsm4(ah0,ah1,ah2,ah3, sAh + aOff + kB);
        if(ALO) ldsm4(al0,al1,al2,al3, sAl + aOff + kB);
        #pragma unroll
        for(int np=0;np<NC/2;np++){
            u32 bb = sBh + bOff + kB + (u32)(np*2304);
            u32 bh0,bh1,bh2,bh3, bl0,bl1,bl2,bl3;
            ldsm4(bh0,bh1,bh2,bh3, bb);
            if(BLO) ldsm4(bl0,bl1,bl2,bl3, (sBl - sBh) + bb);
            float* c0=cc+np*8; float* c1=cc+np*8+4;
            MMA4(c0,ah0,ah1,ah2,ah3,bh0,bh1);
            if(BLO) MMA4(c0,ah0,ah1,ah2,ah3,bl0,bl1);
            if(ALO) MMA4(c0,al0,al1,al2,al3,bh0,bh1);
            MMA4(c1,ah0,ah1,ah2,ah3,bh2,bh3);
            if(BLO) MMA4(c1,ah0,ah1,ah2,ah3,bl2,bl3);
            if(ALO) MMA4(c1,al0,al1,al2,al3,bh2,bh3);
        }
    }
}

__device__ __forceinline__ void top2ins(float s,int i,float&s1,int&i1,float&s2,int&i2){
    if(s>s1||(s==s1&&i<i1)){ s2=s1;i2=i1;s1=s;i1=i; }
    else if(s>s2||(s==s2&&i<i2)){ s2=s;i2=i; }
}
__device__ __forceinline__ void top2f(float s,int i,float&s1,int&i1,float&s2,int&i2){
    if(s>s1){ s2=s1;i2=i1;s1=s;i1=i; }
    else if(s>s2){ s2=s;i2=i; }
}

// smem byte offsets
#define SA0H 0
#define SA0L 18432
#define SA1H 36864
#define SA1L 55296
#define SBH0 73728
#define SBL0 92160
#define SBH1 110592
#define SBL1 129024
#define ZB   147456
#define W3S  182272
#define HNS  191488
#define VQB  195584
#define SMTOT 199680

// B-chunk schedule: 0-3 w2 | 4-5 w3 | 6-13 cb | 14 d1 | 15-18 d2
__device__ __forceinline__ void issue_chunk(int ci, u32 smb, int tid){
    if(ci>18) return;
    u32 dh = smb + ((ci&1)?SBH1:SBH0);
    u32 dl = smb + ((ci&1)?SBL1:SBL0);
    const hf *gh,*gl=0; long r0=0; int gs,ko,nr=128;
    if(ci<4){ gh=g_w2h; gl=g_w2l; gs=256; ko=ci*64; }
    else if(ci<6){ gh=g_w3h; gl=g_w3l; gs=128; ko=(ci-4)*64; nr=64; }
    else if(ci<14){ gh=g_cbh; gs=64; ko=0; r0=(long)(ci-6)*128; }
    else if(ci==14){ gh=g_d1h; gs=64; ko=0; }
    else { int t=ci-15; gh=g_d2h; gs=128; r0=(long)(t>>1)*128; ko=(t&1)*64; }
    for(int i=tid;i<nr*8;i+=512){
        int r=i>>3, s=i&7;
        const hf* src=gh+(r0+r)*(long)gs+ko+s*8;
        asm volatile("cp.async.ca.shared.global [%0], [%1], 16;"::"r"(dh+(u32)(r*144+s*16)),"l"(src):"memory");
    }
    if(ci<6){
        for(int i=tid;i<nr*8;i+=512){
            int r=i>>3, s=i&7;
            const hf* src=gl+(r0+r)*(long)gs+ko+s*8;
            asm volatile("cp.async.ca.shared.global [%0], [%1], 16;"::"r"(dl+(u32)(r*144+s*16)),"l"(src):"memory");
        }
    }
    asm volatile("cp.async.commit_group;":::"memory");
}
__device__ __forceinline__ void pipe_wait(int ci){
    if(ci<18) asm volatile("cp.async.wait_group 1;":::"memory");
    else      asm volatile("cp.async.wait_group 0;":::"memory");
    __syncthreads();
}

// ---------------- prep ----------------
__global__ void k_prep(const float* __restrict__ w2, const float* __restrict__ w3,
                       const float* __restrict__ d1, const float* __restrict__ d2,
                       const float* __restrict__ cb){
    int i=blockIdx.x*256+threadIdx.x;
    if(i<128*256) fsp(w2[i],g_w2h[i],g_w2l[i]);
    if(i<64*128)  fsp(w3[i],g_w3h[i],g_w3l[i]);
    if(i<128*64)  g_d1h[i]=__float2half_rn(d1[i]);
    if(i<256*128) g_d2h[i]=__float2half_rn(d2[i]);
    if(i<1024*64) g_cbh[i]=__float2half_rn(cb[i]);
    if(i<1024){
        float s=0.f;
        #pragma unroll 8
        for(int d=0;d<64;d++){ float v=cb[i*64+d]; s=fmaf(v,v,s); }
        g_hn[i]=0.5f*s; g_hist[i]=0;
    }
}

// ---------------- fused everything, 512 threads, N-split warp pairs ----------------
__global__ __launch_bounds__(512,1)
void k_main(const float* __restrict__ X,  const float* __restrict__ W1,
            const float* __restrict__ B1, const float* __restrict__ B2,
            const float* __restrict__ B3e,const float* __restrict__ CB,
            const float* __restrict__ DB1,const float* __restrict__ DB2,
            const float* __restrict__ W3d,const float* __restrict__ DB3,
            float* __restrict__ out){
    extern __shared__ char sm[];
    hf* sa0h=(hf*)(sm+SA0H); hf* sa0l=(hf*)(sm+SA0L);
    hf* sa1h=(hf*)(sm+SA1H); hf* sa1l=(hf*)(sm+SA1L);
    float* zbuf=(float*)(sm+ZB);
    float* xs  =(float*)(sm+ZB);
    float* w1s =(float*)(sm+ZB+6144);
    float* psum=(float*)(sm+ZB);       // reused after rescore for dec3 partials
    float* w3s =(float*)(sm+W3S);
    float* hns =(float*)(sm+HNS);
    float* vqb =(float*)(sm+VQB);      // 128 rows x 8 (s1,i1,s2,i2 per wg)
    int*   vqi =(int*)vqb;
    __shared__ float warr[8];
    u32 smb=smem_u32(sm);
    int tid=threadIdx.x, warp=tid>>5, lane=tid&31;
    int wg=warp>>3, w8=warp&7;
    int gi=lane>>2, ti=lane&3, r0w=w8*16, r0=r0w+gi;
    u32 aW=(u32)(r0w*144);
    u32 bW=(u32)(wg*9216);             // +64 B-rows for wg1 (N-split)
    long row0=(long)blockIdx.x*128;

    issue_chunk(0,smb,tid);
    issue_chunk(1,smb,tid);
    for(int i=tid;i<128*9;i+=512){ int r=i/9,k=i-r*9; xs[r*12+k]=X[row0*9+i]; }
    for(int i=tid;i<256*9;i+=512) w1s[i]=W1[i];
    for(int i=tid;i<9*256;i+=512) w3s[i]=W3d[i];
    for(int i=tid;i<1024;i+=512) hns[i]=g_hn[i];
    __syncthreads();

    // ===== enc2 (K=256, 4 chunks; enc1 on the fly; 3-product; N-half/warp) =====
    float acc[32];
    #pragma unroll
    for(int j=0;j<32;j++) acc[j]=0.f;
    for(int ch=0;ch<4;ch++){
        for(int p=tid;p<128*32;p+=512){
            int r=p>>5, cp=p&31, c0=ch*64+2*cp;
            float a0=__ldg(&B1[c0]), a1=__ldg(&B1[c0+1]);
            #pragma unroll
            for(int k=0;k<9;k++){ float xv=xs[r*12+k]; a0=fmaf(xv,w1s[c0*9+k],a0); a1=fmaf(xv,w1s[(c0+1)*9+k],a1); }
            a0=fmaxf(a0,0.f); a1=fmaxf(a1,0.f);
            hf h0,l0,h1,l1; fsp(a0,h0,l0); fsp(a1,h1,l1);
            *(u32*)(sa0h+r*72+2*cp)=hpk(h0,h1);
            *(u32*)(sa0l+r*72+2*cp)=hpk(l0,l1);
        }
        pipe_wait(ch);
        mmaN<8,true,true>(smb+SA0H+aW, smb+SA0L+aW,
                          smb+((ch&1)?SBH1:SBH0)+bW, smb+((ch&1)?SBL1:SBL0)+bW, acc, lane);
        __syncthreads();
        issue_chunk(ch+2,smb,tid);
    }
    // h2 = relu(acc+b2): wg0 -> SA0 (cols 0-63), wg1 -> SA1 (cols 64-127)
    {
        hf* dh = wg?sa1h:sa0h; hf* dl = wg?sa1l:sa0l;
        #pragma unroll
        for(int nc=0;nc<8;nc++){
            int cl=nc*8+2*ti, c=wg*64+cl;
            float b0=__ldg(&B2[c]), b1=__ldg(&B2[c+1]);
            float v0=fmaxf(acc[nc*4+0]+b0,0.f), v1=fmaxf(acc[nc*4+1]+b1,0.f);
            float v2=fmaxf(acc[nc*4+2]+b0,0.f), v3=fmaxf(acc[nc*4+3]+b1,0.f);
            hf h0,l0,h1,l1;
            fsp(v0,h0,l0); fsp(v1,h1,l1);
            *(u32*)(dh+r0*72+cl)=hpk(h0,h1); *(u32*)(dl+r0*72+cl)=hpk(l0,l1);
            fsp(v2,h0,l0); fsp(v3,h1,l1);
            *(u32*)(dh+(r0+8)*72+cl)=hpk(h0,h1); *(u32*)(dl+(r0+8)*72+cl)=hpk(l0,l1);
        }
    }
    // ===== enc3 (K=128, 2 chunks, 3-product, N=64 -> 32/warp) =====
    float c3[16];
    #pragma unroll
    for(int j=0;j<16;j++) c3[j]=0.f;
    for(int ch=0;ch<2;ch++){
        pipe_wait(4+ch);
        u32 ah=smb+(ch?SA1H:SA0H)+aW, al=smb+(ch?SA1L:SA0L)+aW;
        mmaN<4,true,true>(ah,al,
                          smb+(((4+ch)&1)?SBH1:SBH0)+(u32)(wg*4608),
                          smb+(((4+ch)&1)?SBL1:SBL0)+(u32)(wg*4608),c3,lane);
        __syncthreads();
        issue_chunk(6+ch,smb,tid);
    }
    // z -> zbuf fp32 + fp16 plane in SA0H (cols split by wg)
    #pragma unroll
    for(int nc=0;nc<4;nc++){
        int c=wg*32+nc*8+2*ti;
        float b0=__ldg(&B3e[c]), b1=__ldg(&B3e[c+1]);
        float z00=c3[nc*4+0]+b0, z01=c3[nc*4+1]+b1;
        float z10=c3[nc*4+2]+b0, z11=c3[nc*4+3]+b1;
        zbuf[r0*68+c]=z00; zbuf[r0*68+c+1]=z01;
        zbuf[(r0+8)*68+c]=z10; zbuf[(r0+8)*68+c+1]=z11;
        *(u32*)(sa0h+r0*72+c)=hpk(__float2half_rn(z00),__float2half_rn(z01));
        *(u32*)(sa0h+(r0+8)*72+c)=hpk(__float2half_rn(z10),__float2half_rn(z11));
    }
    // ===== VQ scan (1-product; each warp scans its 64-col half of each tile) =====
    float s1[2]={-3.4e38f,-3.4e38f}, s2v[2]={-3.4e38f,-3.4e38f};
    int   i1[2]={0,0}, i2[2]={0,0};
    for(int t=0;t<8;t++){
        pipe_wait(6+t);
        float cv[32];
        #pragma unroll
        for(int j=0;j<32;j++) cv[j]=0.f;
        mmaN<8,false,false>(smb+SA0H+aW, 0u,
                            smb+(((6+t)&1)?SBH1:SBH0)+bW, 0u, cv, lane);
        #pragma unroll
        for(int nc=0;nc<8;nc++){
            #pragma unroll
            for(int cc=0;cc<2;cc++){
                int col=t*128+wg*64+nc*8+2*ti+cc;
                float hn=hns[col];
                top2f(cv[nc*4+cc]-hn,  col, s1[0],i1[0],s2v[0],i2[0]);
                top2f(cv[nc*4+2+cc]-hn,col, s1[1],i1[1],s2v[1],i2[1]);
            }
        }
        __syncthreads();
        issue_chunk(8+t,smb,tid);
    }
    // merge top-2 across ti lanes (tie-aware)
    #pragma unroll
    for(int off=1;off<=2;off<<=1){
        #pragma unroll
        for(int s=0;s<2;s++){
            float os1=__shfl_xor_sync(0xffffffffu,s1[s],off);
            int   oi1=__shfl_xor_sync(0xffffffffu,i1[s],off);
            float os2=__shfl_xor_sync(0xffffffffu,s2v[s],off);
            int   oi2=__shfl_xor_sync(0xffffffffu,i2[s],off);
            top2ins(os1,oi1,s1[s],i1[s],s2v[s],i2[s]);
            top2ins(os2,oi2,s1[s],i1[s],s2v[s],i2[s]);
        }
    }
    // publish per-half top2 to smem
    if(ti==0){
        #pragma unroll
        for(int s=0;s<2;s++){
            int row=r0+s*8, base=row*8+wg*4;
            vqb[base]=s1[s]; vqi[base+1]=i1[s]; vqb[base+2]=s2v[s]; vqi[base+3]=i2[s];
        }
    }
    __syncthreads();
    // wg0 merges halves, exact-rescores top-2, writes q plane + hist + mse
    float lsum=0.f;
    if(wg==0){
        #pragma unroll
        for(int s=0;s<2;s++){
            int row=r0+s*8, base=row*8+4;
            top2ins(vqb[base],  vqi[base+1], s1[s],i1[s],s2v[s],i2[s]);
            top2ins(vqb[base+2],vqi[base+3], s1[s],i1[s],s2v[s],i2[s]);
            const float* z=&zbuf[row*68];
            int ca=i1[s], cb=i2[s];
            float da=0.f,db=0.f;
            #pragma unroll 4
            for(int q=0;q<16;q++){
                float4 v1=__ldg((const float4*)&CB[(long)ca*64+q*4]);
                float4 v2=__ldg((const float4*)&CB[(long)cb*64+q*4]);
                float4 zv=*(const float4*)(z+q*4);
                da=fmaf(v1.x-zv.x,v1.x-zv.x,da); da=fmaf(v1.y-zv.y,v1.y-zv.y,da);
                da=fmaf(v1.z-zv.z,v1.z-zv.z,da); da=fmaf(v1.w-zv.w,v1.w-zv.w,da);
                db=fmaf(v2.x-zv.x,v2.x-zv.x,db); db=fmaf(v2.y-zv.y,v2.y-zv.y,db);
                db=fmaf(v2.z-zv.z,v2.z-zv.z,db); db=fmaf(v2.w-zv.w,v2.w-zv.w,db);
            }
            int cw; float dw;
            if(da<db||(da==db&&ca<cb)){ cw=ca; dw=da; } else { cw=cb; dw=db; }
            if(ti==0){ atomicAdd(&g_hist[cw],1); lsum+=dw; }
            #pragma unroll
            for(int q=0;q<4;q++){
                float4 v=__ldg((const float4*)&CB[(long)cw*64+ti*16+q*4]);
                *(u32*)(sa0h+row*72+ti*16+q*4)  =hpk(__float2half_rn(v.x),__float2half_rn(v.y));
                *(u32*)(sa0h+row*72+ti*16+q*4+2)=hpk(__float2half_rn(v.z),__float2half_rn(v.w));
            }
        }
        #pragma unroll
        for(int o=16;o;o>>=1) lsum+=__shfl_xor_sync(0xffffffffu,lsum,o);
        if(lane==0) warr[w8]=lsum;
    }
    // ===== dec1 (K=64, 1-product, N-half/warp) =====
    float c1[32];
    #pragma unroll
    for(int j=0;j<32;j++) c1[j]=0.f;
    pipe_wait(14);
    mmaN<8,false,false>(smb+SA0H+aW, 0u, smb+SBH0+bW, 0u, c1, lane);
    __syncthreads();
    issue_chunk(16,smb,tid);
    {
        hf* dh = wg?sa1h:sa0h;
        #pragma unroll
        for(int nc=0;nc<8;nc++){
            int cl=nc*8+2*ti, c=wg*64+cl;
            float b0=__ldg(&DB1[c]), b1=__ldg(&DB1[c+1]);
            float v0=fmaxf(c1[nc*4+0]+b0,0.f), v1=fmaxf(c1[nc*4+1]+b1,0.f);
            float v2=fmaxf(c1[nc*4+2]+b0,0.f), v3=fmaxf(c1[nc*4+3]+b1,0.f);
            *(u32*)(dh+r0*72+cl)=hpk(__float2half_rn(v0),__float2half_rn(v1));
            *(u32*)(dh+(r0+8)*72+cl)=hpk(__float2half_rn(v2),__float2half_rn(v3));
        }
    }
    // ===== dec2 (2 N-halves x 2 K-chunks, 1-product) + dec3 partials =====
    float part[2][9];
    #pragma unroll
    for(int s=0;s<2;s++)
        #pragma unroll
        for(int j=0;j<9;j++) part[s][j]=0.f;
    for(int nh=0;nh<2;nh++){
        float c2[32];
        #pragma unroll
        for(int j=0;j<32;j++) c2[j]=0.f;
        for(int kc=0;kc<2;kc++){
            int ci=15+nh*2+kc;
            pipe_wait(ci);
            u32 ah=smb+(kc?SA1H:SA0H)+aW;
            mmaN<8,false,false>(ah, 0u, smb+((ci&1)?SBH1:SBH0)+bW, 0u, c2, lane);
            __syncthreads();
            issue_chunk(ci+2,smb,tid);
        }
        #pragma unroll
        for(int nc=0;nc<8;nc++){
            #pragma unroll
            for(int cc=0;cc<2;cc++){
                int c=nh*128+wg*64+nc*8+2*ti+cc;
                float b=__ldg(&DB2[c]);
                float v0=fmaxf(c2[nc*4+cc]+b,0.f);
                float v1=fmaxf(c2[nc*4+2+cc]+b,0.f);
                #pragma unroll
                for(int j=0;j<9;j++){
                    float w=w3s[j*256+c];
                    part[0][j]=fmaf(v0,w,part[0][j]);
                    part[1][j]=fmaf(v1,w,part[1][j]);
                }
            }
        }
    }
    #pragma unroll
    for(int off=1;off<=2;off<<=1)
        #pragma unroll
        for(int s=0;s<2;s++)
            #pragma unroll
            for(int j=0;j<9;j++) part[s][j]+=__shfl_xor_sync(0xffffffffu,part[s][j],off);
    if(ti==0){
        #pragma unroll
        for(int s=0;s<2;s++){
            int row=r0+s*8;
            #pragma unroll
            for(int j=0;j<9;j++) psum[row*18+wg*9+j]=part[s][j];
        }
    }
    __syncthreads();
    for(int i=tid;i<128*9;i+=512){
        int row=i/9, j=i-row*9;
        out[(row0+row)*9+j]=psum[row*18+j]+psum[row*18+9+j]+__ldg(&DB3[j]);
    }
    if(tid==0){
        float s=0.f;
        #pragma unroll
        for(int w=0;w<8;w++) s+=warr[w];
        g_msep[blockIdx.x]=s;
    }
}

// ---------------- finalize ----------------
__global__ void k_final(float* __restrict__ out){
    __shared__ double sd[1024];
    __shared__ double mt;
    int tid=threadIdx.x;
    sd[tid]=(double)g_msep[tid]+(double)g_msep[tid+1024];
    __syncthreads();
    for(int o=512;o;o>>=1){ if(tid<o) sd[tid]+=sd[tid+o]; __syncthreads(); }
    if(tid==0) mt=sd[0];
    __syncthreads();
    float p=(float)g_hist[tid]/262144.0f;
    sd[tid]=(double)(p*logf(p+1e-10f));
    __syncthreads();
    for(int o=512;o;o>>=1){ if(tid<o) sd[tid]+=sd[tid+o]; __syncthreads(); }
    if(tid==0){
        float mse=(float)(mt/(262144.0*64.0));
        out[262144*9+0]=1.25f*mse;
        out[262144*9+1]=expf(-(float)sd[0]);
    }
}

// ---------------------------------------------------------------------------
extern "C" void kernel_launch(void* const* d_in, const int* in_sizes, int n_in,
                              void* d_out, int out_size){
    const float* x  =(const float*)d_in[0];
    const float* ew1=(const float*)d_in[1];  const float* eb1=(const float*)d_in[2];
    const float* ew2=(const float*)d_in[3];  const float* eb2=(const float*)d_in[4];
    const float* ew3=(const float*)d_in[5];  const float* eb3=(const float*)d_in[6];
    const float* dw1=(const float*)d_in[7];  const float* db1=(const float*)d_in[8];
    const float* dw2=(const float*)d_in[9];  const float* db2=(const float*)d_in[10];
    const float* dw3=(const float*)d_in[11]; const float* db3=(const float*)d_in[12];
    const float* cb =(const float*)d_in[13];
    float* out=(float*)d_out;

    cudaFuncSetAttribute(k_main, cudaFuncAttributeMaxDynamicSharedMemorySize, SMTOT);

    k_prep<<<256,256>>>(ew2, ew3, dw1, dw2, cb);
    k_main<<<GRD,512,SMTOT>>>(x, ew1, eb1, eb2, eb3, cb, db1, db2, dw3, db3, out);
    k_final<<<1,1024>>>(out);
}